// round 8
// baseline (speedup 1.0000x reference)
#include <cuda_runtime.h>
#include <cuda_bf16.h>
#include <math.h>
#include <stdint.h>

// ---------------- problem constants ----------------
#define Bn   16
#define Nn   3136        // 56*56
#define Cn   512
#define NH   8
#define HD   64
#define Fn   128         // 2*HD
#define Mrows (Bn*Nn)    // 50176
#define HW   56

// ---------------- scratch (device globals; no allocs allowed) --------------
__device__ __align__(16) float d_qgkv[Mrows * 2048];        // [b,n, q|g|k|v] (512 each)
__device__ __align__(16) float d_xr[Mrows * 512];           // x, tf32, FRAGMENT layout
__device__ __align__(16) __nv_bfloat16 d_qf[Bn*NH*Nn*Fn];   // q_sim  [bh,n,128] bf16
__device__ __align__(16) __nv_bfloat16 d_kf[Bn*NH*Nn*Fn];   // kf     [bh,n,128] bf16
__device__ __align__(16) float d_km[Bn*NH*Fn];              // mean over n
__device__ __align__(16) float d_kvm[Bn*NH*Fn*64];          // [bh,d(128),e(64)]
__device__ __align__(16) float d_kvm2[Bn*NH*Fn*72];         // [bh,d(128),72] B for attn
__device__ __align__(16) float d_t [Mrows * Cn];            // (xo+vd)*g, tf32, FRAGMENT layout
__device__ __align__(16) float d_wtc[2048 * 512];           // [qg_w|kv_w]^T tf32, FRAGMENT
__device__ __align__(16) float d_wt3[512 * 512];            // proj_w^T tf32, FRAGMENT
__device__ __align__(16) float d_scinv[Cn];
__device__ __align__(16) float d_pw[Cn];

// =====================================================================
// helpers (baseline PTX only)
// =====================================================================
__device__ __forceinline__ uint32_t smem_u32(const void* p) {
    uint32_t a;
    asm("{ .reg .u64 t; cvta.to.shared.u64 t, %1; cvt.u32.u64 %0, t; }"
        : "=r"(a) : "l"(p));
    return a;
}

__device__ __forceinline__ float to_tf32(float x) {
    float r;
    asm("cvt.rna.tf32.f32 %0, %1;" : "=f"(r) : "f"(x));
    return r;
}

__device__ __forceinline__ void cp_async16(uint32_t saddr, const void* gaddr) {
    asm volatile("cp.async.ca.shared.global [%0], [%1], 16;"
                 :: "r"(saddr), "l"(gaddr) : "memory");
}
#define CP_COMMIT() asm volatile("cp.async.commit_group;" ::: "memory")
#define CP_WAIT(N)  asm volatile("cp.async.wait_group %0;" :: "n"(N) : "memory")

__device__ __forceinline__ void mma_tf32_16_8_8(float* c, const uint32_t* a,
                                                uint32_t b0, uint32_t b1) {
    asm volatile(
        "mma.sync.aligned.m16n8k8.row.col.f32.tf32.tf32.f32 "
        "{%0,%1,%2,%3}, {%4,%5,%6,%7}, {%8,%9}, {%0,%1,%2,%3};"
        : "+f"(c[0]), "+f"(c[1]), "+f"(c[2]), "+f"(c[3])
        : "r"(a[0]), "r"(a[1]), "r"(a[2]), "r"(a[3]), "r"(b0), "r"(b1));
}

__device__ __forceinline__ uint32_t bf_as_tf32(uint16_t h) {
    __nv_bfloat16 b = *reinterpret_cast<__nv_bfloat16*>(&h);
    return __float_as_uint(__bfloat162float(b));
}

// fragment-order permutation for K=512 operand panels of 128 rows.
__device__ __forceinline__ size_t perm_idx(int r, int k) {
    return (size_t)(r >> 7) * 65536
         + (size_t)((((k >> 3) * 8 + ((r >> 4) & 7)) << 7)
         + (((r & 7) * 4 + (k & 3)) << 2)
         + ((r >> 3) & 1) + (((k >> 2) & 1) << 1));
}

// =====================================================================
// tensor-core tf32 GEMM: C[M,Nc] = A[M,512] @ Bt[Nc,512]^T (+bias)
// A, Bt in FRAGMENT layout. CTA 128x256, 8 warps (2m x 4n), warp 64x64.
// 3-stage cp.async pipeline, ONE barrier per k-tile.
// =====================================================================
#define GEMM_SMEM (3 * 12288 * 4)      // 3 stages x 48KB = 147456 B

__global__ __launch_bounds__(256, 1)
void gemm_mma(const float* __restrict__ A, const float* __restrict__ Bt,
              const float* __restrict__ bias, float* __restrict__ Cm, int Nc)
{
    extern __shared__ float sm[];
    float* stage[3] = { sm, sm + 12288, sm + 24576 };
    const int tid = threadIdx.x;
    const int bn0 = blockIdx.x * 256;
    const int bm_panel = blockIdx.y;
    const int wid = tid >> 5, lane = tid & 31;
    const int lr = lane >> 2, lc = lane & 3;
    const int wm  = (wid & 1) * 64;
    const int wm4 = (wid & 1) * 4;
    const int wn  = (wid >> 1) * 64;
    const int wng = (wid >> 1) * 4;

    const float* Ab  = A  + (size_t)bm_panel * 65536;
    const float* Bb0 = Bt + (size_t)(bn0 >> 7) * 65536;
    const float* Bb1 = Bb0 + 65536;

    float c[4][8][4];
#pragma unroll
    for (int mt = 0; mt < 4; mt++)
#pragma unroll
        for (int nt = 0; nt < 8; nt++)
#pragma unroll
            for (int j = 0; j < 4; j++) c[mt][nt][j] = 0.f;

    auto issue_stage = [&](int buf, int t) {
        uint32_t sa = smem_u32(stage[buf]);
        const float* as = Ab  + t * 4096;
        const float* b0 = Bb0 + t * 4096;
        const float* b1 = Bb1 + t * 4096;
#pragma unroll
        for (int i = 0; i < 4; i++) {
            int ch = tid + i * 256;
            cp_async16(sa + ch * 16, as + ch * 4);
        }
#pragma unroll
        for (int i = 0; i < 4; i++) {
            int ch = tid + i * 256;
            cp_async16(sa + 16384 + ch * 16, b0 + ch * 4);
        }
#pragma unroll
        for (int i = 0; i < 4; i++) {
            int ch = tid + i * 256;
            cp_async16(sa + 32768 + ch * 16, b1 + ch * 4);
        }
        CP_COMMIT();
    };

    issue_stage(0, 0);
    issue_stage(1, 1);

    for (int t = 0; t < 16; t++) {
        CP_WAIT(1);                       // stage t resident
        __syncthreads();                  // visible to all; stage t-1 buffer free
        if (t + 2 < 16) issue_stage((t + 2) % 3, t + 2);
        else            CP_COMMIT();      // empty group keeps wait arithmetic exact

        const float4* sa4 = (const float4*)stage[t % 3];
        const float4* sb4 = (const float4*)(stage[t % 3] + 4096);
#pragma unroll
        for (int kk = 0; kk < 4; kk++) {
            uint32_t a[4][4];
            float4 bv[4];
#pragma unroll
            for (int mt = 0; mt < 4; mt++) {
                float4 v = sa4[(kk * 8 + wm4 + mt) * 32 + lane];
                a[mt][0] = __float_as_uint(v.x);
                a[mt][1] = __float_as_uint(v.y);
                a[mt][2] = __float_as_uint(v.z);
                a[mt][3] = __float_as_uint(v.w);
            }
#pragma unroll
            for (int p = 0; p < 4; p++) {
                int g = wng + p;
                bv[p] = sb4[(g >> 3) * 1024 + (kk * 8 + (g & 7)) * 32 + lane];
            }
#pragma unroll
            for (int mt = 0; mt < 4; mt++)
#pragma unroll
                for (int p = 0; p < 4; p++) {
                    mma_tf32_16_8_8(c[mt][2 * p],
                                    a[mt], __float_as_uint(bv[p].x),
                                           __float_as_uint(bv[p].z));
                    mma_tf32_16_8_8(c[mt][2 * p + 1],
                                    a[mt], __float_as_uint(bv[p].y),
                                           __float_as_uint(bv[p].w));
                }
        }
    }

#pragma unroll
    for (int mt = 0; mt < 4; mt++) {
        int row = bm_panel * 128 + wm + mt * 16 + lr;
#pragma unroll
        for (int nt = 0; nt < 8; nt++) {
            int col = bn0 + wn + nt * 8 + lc * 2;
            float2 v0 = make_float2(c[mt][nt][0], c[mt][nt][1]);
            float2 v1 = make_float2(c[mt][nt][2], c[mt][nt][3]);
            if (bias) {
                float b0 = bias[col], b1 = bias[col + 1];
                v0.x += b0; v0.y += b1;
                v1.x += b0; v1.y += b1;
            }
            *(float2*)&Cm[(size_t)row * Nc + col] = v0;
            *(float2*)&Cm[(size_t)(row + 8) * Nc + col] = v1;
        }
    }
}

// =====================================================================
// weight transposes -> fragment layout, tf32
// =====================================================================
__global__ void transpose_qgkv(const float* __restrict__ qg_w,
                               const float* __restrict__ kv_w)
{
    __shared__ float t[32][33];
    int bx = blockIdx.x * 32;
    int by = blockIdx.y * 32;
    int x = threadIdx.x, y = threadIdx.y;
    const float* W = (bx < 1024) ? qg_w : kv_w;
    int nb = bx & 1023;
#pragma unroll
    for (int j = 0; j < 32; j += 8)
        t[y + j][x] = W[(size_t)(by + y + j) * 1024 + nb + x];
    __syncthreads();
#pragma unroll
    for (int j = 0; j < 32; j += 8)
        d_wtc[perm_idx(bx + y + j, by + x)] = to_tf32(t[x][y + j]);
}

__global__ void transpose_w(const float* __restrict__ W, float* __restrict__ Wt, int Nc)
{
    __shared__ float t[32][33];
    int bx = blockIdx.x * 32;
    int by = blockIdx.y * 32;
    int x = threadIdx.x, y = threadIdx.y;
#pragma unroll
    for (int j = 0; j < 32; j += 8)
        t[y + j][x] = W[(size_t)(by + y + j) * Nc + bx + x];
    __syncthreads();
#pragma unroll
    for (int j = 0; j < 32; j += 8)
        Wt[perm_idx(bx + y + j, by + x)] = to_tf32(t[x][y + j]);
}

// =====================================================================
// x -> tf32 fragment layout
// =====================================================================
__global__ void permute_x(const float* __restrict__ x)
{
    int idx = blockIdx.x * 256 + threadIdx.x;
    int r = idx >> 7;
    int k = (idx & 127) * 4;
    float4 v = ((const float4*)x)[idx];
    size_t base = perm_idx(r, k);
    d_xr[base]      = to_tf32(v.x);
    d_xr[base + 4]  = to_tf32(v.y);
    d_xr[base + 8]  = to_tf32(v.z);
    d_xr[base + 12] = to_tf32(v.w);
}

// =====================================================================
// per-channel params
// =====================================================================
__global__ void prep_params(const float* __restrict__ scale_p,
                            const float* __restrict__ power_p)
{
    int c = threadIdx.x;
    d_scinv[c] = 1.f / log1pf(expf(scale_p[c]));
    d_pw[c] = 1.f + 4.f / (1.f + expf(-power_p[c]));
}

// =====================================================================
// features + fused km
// =====================================================================
__global__ __launch_bounds__(512)
void features_kernel(const float* __restrict__ pos_enc)
{
    int c   = threadIdx.x;
    int h   = c >> 6;
    int d   = c & 63;
    int bn0 = blockIdx.x * 16;
    int b   = bn0 / Nn;
    int n0  = bn0 - b * Nn;

    float scinv = d_scinv[c];
    float pw    = d_pw[c];
    float skp = 0.f, skn = 0.f;

#pragma unroll 4
    for (int i = 0; i < 16; i++) {
        int bn_ = bn0 + i;
        int n   = n0 + i;
        float qv  = d_qgkv[(size_t)bn_ * 2048 + c] * scinv;
        float kvv = (d_qgkv[(size_t)bn_ * 2048 + 1024 + c] + pos_enc[n * Cn + c]) * scinv;

        float qa = exp2f(pw * __log2f(fabsf(qv)));
        float ka = exp2f(pw * __log2f(fabsf(kvv)));
        float qp = (qv  > 0.f) ? qa : 0.f;
        float qn = (qv  < 0.f) ? qa : 0.f;
        float kp = (kvv > 0.f) ? ka : 0.f;
        float kn = (kvv < 0.f) ? ka : 0.f;

        size_t fbase = ((size_t)(b * NH + h) * Nn + n) * Fn;
        d_qf[fbase + d]      = __float2bfloat16_rn(qp);
        d_qf[fbase + 64 + d] = __float2bfloat16_rn(qn);
        d_kf[fbase + d]      = __float2bfloat16_rn(kp);
        d_kf[fbase + 64 + d] = __float2bfloat16_rn(kn);
        skp += kp; skn += kn;
    }
    const float inv_n = 1.f / (float)Nn;
    atomicAdd(&d_km[(b * NH + h) * Fn + d],      skp * inv_n);
    atomicAdd(&d_km[(b * NH + h) * Fn + 64 + d], skn * inv_n);
}

// =====================================================================
// zero km + kvm accumulators
// =====================================================================
__global__ void zero_aux_kernel()
{
    int i = blockIdx.x * blockDim.x + threadIdx.x;
    int stride = gridDim.x * blockDim.x;
    if (i < Bn * NH * Fn) d_km[i] = 0.f;
    for (int j = i; j < Bn * NH * Fn * 64; j += stride) d_kvm[j] = 0.f;
}

// =====================================================================
// kvm via mma
// =====================================================================
#define KV_SEG 1568

__global__ __launch_bounds__(256)
void kvm_mma()
{
    __shared__ __align__(16) uint16_t kfs[2][32][136];
    __shared__ __align__(16) float    vss[2][32][72];
    int bh = blockIdx.x, seg = blockIdx.y;
    int b = bh >> 3, h = bh & 7;
    int tid = threadIdx.x, wid = tid >> 5, lane = tid & 31;
    int lr = lane >> 2, lc = lane & 3;
    int wd = (wid & 1) * 64;
    int we = (wid >> 1) * 16;

    float c[4][2][4];
#pragma unroll
    for (int mt = 0; mt < 4; mt++)
#pragma unroll
        for (int nt = 0; nt < 2; nt++)
#pragma unroll
            for (int j = 0; j < 4; j++) c[mt][nt][j] = 0.f;

    int nbase = seg * KV_SEG;
#pragma unroll
    for (int j = 0; j < 2; j++) {
        int idx = tid + j * 256;
        int r = idx >> 4, cs = idx & 15;
        cp_async16(smem_u32(&kfs[0][r][cs * 8]),
                   &d_kf[((size_t)bh * Nn + nbase + r) * 128 + cs * 8]);
        cp_async16(smem_u32(&vss[0][r][cs * 4]),
                   &d_qgkv[((size_t)(b * Nn) + nbase + r) * 2048 + 1536 + h * 64 + cs * 4]);
    }
    CP_COMMIT();

    for (int t = 0; t < 49; t++) {
        if (t + 1 < 49) {
            int nb = (t + 1) & 1;
            int n0 = nbase + (t + 1) * 32;
#pragma unroll
            for (int j = 0; j < 2; j++) {
                int idx = tid + j * 256;
                int r = idx >> 4, cs = idx & 15;
                cp_async16(smem_u32(&kfs[nb][r][cs * 8]),
                           &d_kf[((size_t)bh * Nn + n0 + r) * 128 + cs * 8]);
                cp_async16(smem_u32(&vss[nb][r][cs * 4]),
                           &d_qgkv[((size_t)(b * Nn) + n0 + r) * 2048 + 1536 + h * 64 + cs * 4]);
            }
            CP_COMMIT();
            CP_WAIT(1);
        } else {
            CP_WAIT(0);
        }
        __syncthreads();
        int buf = t & 1;
#pragma unroll
        for (int kk = 0; kk < 4; kk++) {
            int k0 = kk * 8;
            uint32_t a[4][4];
#pragma unroll
            for (int mt = 0; mt < 4; mt++) {
                int db = wd + mt * 16;
                a[mt][0] = bf_as_tf32(kfs[buf][k0 + lc][db + lr]);
                a[mt][1] = bf_as_tf32(kfs[buf][k0 + lc][db + lr + 8]);
                a[mt][2] = bf_as_tf32(kfs[buf][k0 + lc + 4][db + lr]);
                a[mt][3] = bf_as_tf32(kfs[buf][k0 + lc + 4][db + lr + 8]);
            }
#pragma unroll
            for (int nt = 0; nt < 2; nt++) {
                int eb = we + nt * 8;
                uint32_t b0 = __float_as_uint(vss[buf][k0 + lc][eb + lr]);
                uint32_t b1 = __float_as_uint(vss[buf][k0 + lc + 4][eb + lr]);
#pragma unroll
                for (int mt = 0; mt < 4; mt++)
                    mma_tf32_16_8_8(c[mt][nt], a[mt], b0, b1);
            }
        }
        __syncthreads();
    }

    const float inv_n = 1.f / (float)Nn;
    float* dst = &d_kvm[(size_t)bh * 8192];
#pragma unroll
    for (int mt = 0; mt < 4; mt++) {
        int d0 = wd + mt * 16 + lr;
#pragma unroll
        for (int nt = 0; nt < 2; nt++) {
            int e0 = we + nt * 8 + 2 * lc;
            atomicAdd(&dst[d0 * 64 + e0],           c[mt][nt][0] * inv_n);
            atomicAdd(&dst[d0 * 64 + e0 + 1],       c[mt][nt][1] * inv_n);
            atomicAdd(&dst[(d0 + 8) * 64 + e0],     c[mt][nt][2] * inv_n);
            atomicAdd(&dst[(d0 + 8) * 64 + e0 + 1], c[mt][nt][3] * inv_n);
        }
    }
}

// =====================================================================
// build KVM2
// =====================================================================
__global__ void build_kvm2()
{
    int bh = blockIdx.x;
    const float* kvm = &d_kvm[(size_t)bh * 8192];
    const float* km  = &d_km[bh * 128];
    float* out = &d_kvm2[(size_t)bh * 9216];
    for (int i = threadIdx.x; i < 128 * 72; i += 256) {
        int dd = i / 72, col = i - dd * 72;
        float v;
        if (col < 32)       v = kvm[dd * 64 + col];
        else if (col < 64)  v = kvm[(dd ^ 64) * 64 + col];
        else if (col == 64) v = km[dd];
        else if (col == 65) v = km[dd ^ 64];
        else                v = 0.f;
        out[i] = v;
    }
}

// =====================================================================
// attention via mma; scatter-stores d_t in FRAGMENT layout
// =====================================================================
#define ATT_SMEM (36864 + 17408)

__global__ __launch_bounds__(128)
void attn_mma()
{
    extern __shared__ char smx[];
    float*    Bsm = (float*)smx;
    uint16_t* Asm = (uint16_t*)(smx + 36864);
    int m0 = blockIdx.x * 64, bh = blockIdx.y;
    int b = bh >> 3, h = bh & 7;
    int tid = threadIdx.x, wid = tid >> 5, lane = tid & 31;
    int lr = lane >> 2, lc = lane & 3;
    int wm = wid * 16;

    {
        const char* bsrc = (const char*)&d_kvm2[(size_t)bh * 9216];
#pragma unroll
        for (int j = 0; j < 18; j++) {
            int idx = tid + j * 128;
            cp_async16(smem_u32((char*)Bsm + idx * 16), bsrc + idx * 16);
        }
#pragma unroll
        for (int j = 0; j < 8; j++) {
            int idx = tid + j * 128;
            int r = idx >> 4, cs = idx & 15;
            cp_async16(smem_u32(&Asm[r * 136 + cs * 8]),
                       &d_qf[((size_t)bh * Nn + m0 + r) * 128 + cs * 8]);
        }
        CP_COMMIT(); CP_WAIT(0);
    }
    __syncthreads();

    float c[9][4];
#pragma unroll
    for (int nt = 0; nt < 9; nt++)
#pragma unroll
        for (int j = 0; j < 4; j++) c[nt][j] = 0.f;

#pragma unroll
    for (int kt = 0; kt < 16; kt++) {
        int k0 = kt * 8;
        uint32_t a[4];
        a[0] = bf_as_tf32(Asm[(wm + lr) * 136 + k0 + lc]);
        a[1] = bf_as_tf32(Asm[(wm + lr + 8) * 136 + k0 + lc]);
        a[2] = bf_as_tf32(Asm[(wm + lr) * 136 + k0 + lc + 4]);
        a[3] = bf_as_tf32(Asm[(wm + lr + 8) * 136 + k0 + lc + 4]);
#pragma unroll
        for (int nt = 0; nt < 9; nt++) {
            uint32_t b0 = __float_as_uint(Bsm[(k0 + lc) * 72 + nt * 8 + lr]);
            uint32_t b1 = __float_as_uint(Bsm[(k0 + lc + 4) * 72 + nt * 8 + lr]);
            mma_tf32_16_8_8(c[nt], a, b0, b1);
        }
    }

    int src = lane & 28;
    float den1a = __shfl_sync(0xffffffffu, c[8][0], src);
    float den2a = __shfl_sync(0xffffffffu, c[8][1], src);
    float den1b = __shfl_sync(0xffffffffu, c[8][2], src);
    float den2b = __shfl_sync(0xffffffffu, c[8][3], src);
    float z1a = 1.f / (den1a + 1e-6f), z2a = 1.f / (den2a + 1e-6f);
    float z1b = 1.f / (den1b + 1e-6f), z2b = 1.f / (den2b + 1e-6f);

    int ra = b * Nn + m0 + wm + lr;
    int rb = ra + 8;
#pragma unroll
    for (int nt = 0; nt < 8; nt++) {
        int col = nt * 8 + 2 * lc;
        float za = (col < 32) ? z1a : z2a;
        float zb = (col < 32) ? z1b : z2b;
        int k = h * 64 + col;
        d_t[perm_idx(ra, k)]     = c[nt][0] * za;
        d_t[perm_idx(ra, k + 1)] = c[nt][1] * za;
        d_t[perm_idx(rb, k)]     = c[nt][2] * zb;
        d_t[perm_idx(rb, k + 1)] = c[nt][3] * zb;
    }
}

// =====================================================================
// depthwise conv + gate; d_t accessed via fragment indices, stores tf32
// =====================================================================
__global__ __launch_bounds__(512)
void conv_gate_kernel(const float* __restrict__ dwc_w,
                      const float* __restrict__ dwc_b)
{
    __shared__ float ws[64 * 25];
    __shared__ float bs[64];
    int y = blockIdx.x;
    int b = blockIdx.y;
    int c = threadIdx.x;
    int d = c & 63;
    for (int i = c; i < 64 * 25; i += 512) ws[i] = dwc_w[i];
    if (c < 64) bs[c] = dwc_b[c];
    __syncthreads();

    const float* vbase = &d_qgkv[(size_t)(b * Nn) * 2048 + 1536 + c];

    float win[5][5];
#pragma unroll
    for (int dy = 0; dy < 5; dy++) {
        int yy = y + dy - 2;
        bool yok = (unsigned)yy < HW;
#pragma unroll
        for (int j = 0; j < 5; j++) {
            int xx = j - 2;
            win[dy][j] = (yok && (unsigned)xx < HW)
                         ? vbase[(size_t)(yy * HW + xx) * 2048] : 0.f;
        }
    }

    for (int x = 0; x < HW; x++) {
        float acc = bs[d];
#pragma unroll
        for (int dy = 0; dy < 5; dy++)
#pragma unroll
            for (int j = 0; j < 5; j++)
                acc = fmaf(win[dy][j], ws[d * 25 + dy * 5 + j], acc);

        int i1 = b * Nn + y * HW + x;
        float g = d_qgkv[(size_t)i1 * 2048 + 512 + c];
        size_t pi = perm_idx(i1, c);
        d_t[pi] = to_tf32((d_t[pi] + acc) * g);

        int xx = x + 3;
        bool xok = xx < HW;
#pragma unroll
        for (int dy = 0; dy < 5; dy++) {
#pragma unroll
            for (int j = 0; j < 4; j++) win[dy][j] = win[dy][j + 1];
            int yy = y + dy - 2;
            win[dy][4] = (xok && (unsigned)yy < HW)
                         ? vbase[(size_t)(yy * HW + xx) * 2048] : 0.f;
        }
    }
}

// =====================================================================
// launch (launch #3 == big gemm for ncu capture)
// =====================================================================
extern "C" void kernel_launch(void* const* d_in, const int* in_sizes, int n_in,
                              void* d_out, int out_size)
{
    const float* x       = (const float*)d_in[0];
    const float* qg_w    = (const float*)d_in[1];
    const float* kv_w    = (const float*)d_in[2];
    const float* proj_w  = (const float*)d_in[3];
    const float* proj_b  = (const float*)d_in[4];
    const float* pos_enc = (const float*)d_in[5];
    const float* scale_p = (const float*)d_in[6];
    const float* power_p = (const float*)d_in[7];
    const float* dwc_w   = (const float*)d_in[8];
    const float* dwc_b   = (const float*)d_in[9];
    float* out = (float*)d_out;

    float *p_qgkv, *p_t, *p_wtc, *p_wt3, *p_xr;
    cudaGetSymbolAddress((void**)&p_qgkv, d_qgkv);
    cudaGetSymbolAddress((void**)&p_t,    d_t);
    cudaGetSymbolAddress((void**)&p_wtc,  d_wtc);
    cudaGetSymbolAddress((void**)&p_wt3,  d_wt3);
    cudaGetSymbolAddress((void**)&p_xr,   d_xr);

    cudaFuncSetAttribute(gemm_mma, cudaFuncAttributeMaxDynamicSharedMemorySize,
                         GEMM_SMEM);
    cudaFuncSetAttribute(attn_mma, cudaFuncAttributeMaxDynamicSharedMemorySize,
                         ATT_SMEM);

    dim3 tb(32, 8);
    prep_params<<<1, 512>>>(scale_p, power_p);                       // 0
    permute_x<<<Mrows * 128 / 256, 256>>>(x);                        // 1
    transpose_qgkv<<<dim3(64, 16), tb>>>(qg_w, kv_w);                // 2
    gemm_mma<<<dim3(8, Mrows / 128), 256, GEMM_SMEM>>>(              // 3 (profiled)
        p_xr, p_wtc, nullptr, p_qgkv, 2048);
    transpose_w<<<dim3(16, 16), tb>>>(proj_w, p_wt3, 512);           // 4
    zero_aux_kernel<<<1024, 256>>>();                                // 5
    features_kernel<<<Mrows / 16, 512>>>(pos_enc);                   // 6
    kvm_mma<<<dim3(Bn * NH, 2), 256>>>();                            // 7
    build_kvm2<<<Bn * NH, 256>>>();                                  // 8
    attn_mma<<<dim3(Nn / 64, Bn * NH), 128, ATT_SMEM>>>();           // 9
    conv_gate_kernel<<<dim3(HW, Bn), 512>>>(dwc_w, dwc_b);           // 10
    gemm_mma<<<dim3(2, Mrows / 128), 256, GEMM_SMEM>>>(              // 11
        p_t, p_wt3, proj_b, out, 512);
}

// round 9
// speedup vs baseline: 1.0404x; 1.0404x over previous
#include <cuda_runtime.h>
#include <cuda_bf16.h>
#include <math.h>
#include <stdint.h>

// ---------------- problem constants ----------------
#define Bn   16
#define Nn   3136        // 56*56
#define Cn   512
#define NH   8
#define HD   64
#define Fn   128         // 2*HD
#define Mrows (Bn*Nn)    // 50176
#define HW   56

// ---------------- scratch (device globals; no allocs allowed) --------------
__device__ __align__(16) float d_qgkv[Mrows * 2048];        // [b,n, q|g|k|v] (512 each)
__device__ __align__(16) float d_xr[Mrows * 512];           // x, tf32, FRAGMENT layout
__device__ __align__(16) __nv_bfloat16 d_qf[Bn*NH*Nn*Fn];   // q_sim  [bh,n,128] bf16
__device__ __align__(16) __nv_bfloat16 d_kf[Bn*NH*Nn*Fn];   // kf     [bh,n,128] bf16
__device__ __align__(16) float d_km[Bn*NH*Fn];              // mean over n
__device__ __align__(16) float d_kvm[Bn*NH*Fn*64];          // [bh,d(128),e(64)]
__device__ __align__(16) float d_kvm2[Bn*NH*Fn*72];         // [bh,d(128),72] B for attn
__device__ __align__(16) float d_t [Mrows * Cn];            // (xo+vd)*g, tf32, FRAGMENT layout
__device__ __align__(16) float d_wtc[2048 * 512];           // [qg_w|kv_w]^T tf32, FRAGMENT
__device__ __align__(16) float d_wt3[512 * 512];            // proj_w^T tf32, FRAGMENT
__device__ __align__(16) float d_scinv[Cn];
__device__ __align__(16) float d_pw[Cn];

// =====================================================================
// helpers (baseline PTX only)
// =====================================================================
__device__ __forceinline__ uint32_t smem_u32(const void* p) {
    uint32_t a;
    asm("{ .reg .u64 t; cvta.to.shared.u64 t, %1; cvt.u32.u64 %0, t; }"
        : "=r"(a) : "l"(p));
    return a;
}

__device__ __forceinline__ float to_tf32(float x) {
    float r;
    asm("cvt.rna.tf32.f32 %0, %1;" : "=f"(r) : "f"(x));
    return r;
}

__device__ __forceinline__ void cp_async16(uint32_t saddr, const void* gaddr) {
    asm volatile("cp.async.ca.shared.global [%0], [%1], 16;"
                 :: "r"(saddr), "l"(gaddr) : "memory");
}
#define CP_COMMIT() asm volatile("cp.async.commit_group;" ::: "memory")
#define CP_WAIT(N)  asm volatile("cp.async.wait_group %0;" :: "n"(N) : "memory")

__device__ __forceinline__ void mma_tf32_16_8_8(float* c, const uint32_t* a,
                                                uint32_t b0, uint32_t b1) {
    asm volatile(
        "mma.sync.aligned.m16n8k8.row.col.f32.tf32.tf32.f32 "
        "{%0,%1,%2,%3}, {%4,%5,%6,%7}, {%8,%9}, {%0,%1,%2,%3};"
        : "+f"(c[0]), "+f"(c[1]), "+f"(c[2]), "+f"(c[3])
        : "r"(a[0]), "r"(a[1]), "r"(a[2]), "r"(a[3]), "r"(b0), "r"(b1));
}

__device__ __forceinline__ uint32_t bf_as_tf32(uint16_t h) {
    __nv_bfloat16 b = *reinterpret_cast<__nv_bfloat16*>(&h);
    return __float_as_uint(__bfloat162float(b));
}

// fragment-order permutation for K=512 operand panels of 128 rows.
__device__ __forceinline__ size_t perm_idx(int r, int k) {
    return (size_t)(r >> 7) * 65536
         + (size_t)((((k >> 3) * 8 + ((r >> 4) & 7)) << 7)
         + (((r & 7) * 4 + (k & 3)) << 2)
         + ((r >> 3) & 1) + (((k >> 2) & 1) << 1));
}

// =====================================================================
// tensor-core tf32 GEMM: C[M,Nc] = A[M,512] @ Bt[Nc,512]^T (+bias)
// A, Bt in FRAGMENT layout. CTA 128x128, 8 warps (2m x 4n), warp 64x32.
// 2 CTAs/SM (phase decorrelation), 3-stage cp.async, 1 barrier/k-tile.
// =====================================================================
#define GEMM_SMEM (3 * 8192 * 4)       // 3 stages x 32KB = 98304 B

__global__ __launch_bounds__(256, 2)
void gemm_mma(const float* __restrict__ A, const float* __restrict__ Bt,
              const float* __restrict__ bias, float* __restrict__ Cm, int Nc)
{
    extern __shared__ float sm[];
    float* stage[3] = { sm, sm + 8192, sm + 16384 };
    const int tid = threadIdx.x;
    const int bn_panel = blockIdx.x;
    const int bm_panel = blockIdx.y;
    const int wid = tid >> 5, lane = tid & 31;
    const int lr = lane >> 2, lc = lane & 3;
    const int wmg = (wid & 1) * 4;       // A 16-row-group base (0 or 4)
    const int wng = (wid >> 1) * 2;      // B 16-col-group base (0,2,4,6)

    const float* Ab = A  + (size_t)bm_panel * 65536;
    const float* Bb = Bt + (size_t)bn_panel * 65536;

    float c[4][4][4];
#pragma unroll
    for (int mt = 0; mt < 4; mt++)
#pragma unroll
        for (int nt = 0; nt < 4; nt++)
#pragma unroll
            for (int j = 0; j < 4; j++) c[mt][nt][j] = 0.f;

    auto issue_stage = [&](int buf, int t) {
        uint32_t sa = smem_u32(stage[buf]);
        const float* as = Ab + t * 4096;
        const float* bs = Bb + t * 4096;
#pragma unroll
        for (int i = 0; i < 4; i++) {
            int ch = tid + i * 256;
            cp_async16(sa + ch * 16, as + ch * 4);
        }
#pragma unroll
        for (int i = 0; i < 4; i++) {
            int ch = tid + i * 256;
            cp_async16(sa + 16384 + ch * 16, bs + ch * 4);
        }
        CP_COMMIT();
    };

    issue_stage(0, 0);
    issue_stage(1, 1);

    for (int t = 0; t < 16; t++) {
        CP_WAIT(1);
        __syncthreads();
        if (t + 2 < 16) issue_stage((t + 2) % 3, t + 2);
        else            CP_COMMIT();

        const float4* sa4 = (const float4*)stage[t % 3];
        const float4* sb4 = (const float4*)(stage[t % 3] + 4096);
#pragma unroll
        for (int kk = 0; kk < 4; kk++) {
            uint32_t a[4][4];
            float4 bv[2];
#pragma unroll
            for (int mt = 0; mt < 4; mt++) {
                float4 v = sa4[(kk * 8 + wmg + mt) * 32 + lane];
                a[mt][0] = __float_as_uint(v.x);
                a[mt][1] = __float_as_uint(v.y);
                a[mt][2] = __float_as_uint(v.z);
                a[mt][3] = __float_as_uint(v.w);
            }
#pragma unroll
            for (int p = 0; p < 2; p++)
                bv[p] = sb4[(kk * 8 + wng + p) * 32 + lane];
#pragma unroll
            for (int mt = 0; mt < 4; mt++)
#pragma unroll
                for (int p = 0; p < 2; p++) {
                    mma_tf32_16_8_8(c[mt][2 * p],
                                    a[mt], __float_as_uint(bv[p].x),
                                           __float_as_uint(bv[p].z));
                    mma_tf32_16_8_8(c[mt][2 * p + 1],
                                    a[mt], __float_as_uint(bv[p].y),
                                           __float_as_uint(bv[p].w));
                }
        }
    }

#pragma unroll
    for (int mt = 0; mt < 4; mt++) {
        int row = bm_panel * 128 + (wid & 1) * 64 + mt * 16 + lr;
#pragma unroll
        for (int nt = 0; nt < 4; nt++) {
            int col = bn_panel * 128 + (wid >> 1) * 32 + nt * 8 + lc * 2;
            float2 v0 = make_float2(c[mt][nt][0], c[mt][nt][1]);
            float2 v1 = make_float2(c[mt][nt][2], c[mt][nt][3]);
            if (bias) {
                float b0 = bias[col], b1 = bias[col + 1];
                v0.x += b0; v0.y += b1;
                v1.x += b0; v1.y += b1;
            }
            *(float2*)&Cm[(size_t)row * Nc + col] = v0;
            *(float2*)&Cm[(size_t)(row + 8) * Nc + col] = v1;
        }
    }
}

// =====================================================================
// weight transposes -> fragment layout, tf32
// =====================================================================
__global__ void transpose_qgkv(const float* __restrict__ qg_w,
                               const float* __restrict__ kv_w)
{
    __shared__ float t[32][33];
    int bx = blockIdx.x * 32;
    int by = blockIdx.y * 32;
    int x = threadIdx.x, y = threadIdx.y;
    const float* W = (bx < 1024) ? qg_w : kv_w;
    int nb = bx & 1023;
#pragma unroll
    for (int j = 0; j < 32; j += 8)
        t[y + j][x] = W[(size_t)(by + y + j) * 1024 + nb + x];
    __syncthreads();
#pragma unroll
    for (int j = 0; j < 32; j += 8)
        d_wtc[perm_idx(bx + y + j, by + x)] = to_tf32(t[x][y + j]);
}

__global__ void transpose_w(const float* __restrict__ W, float* __restrict__ Wt, int Nc)
{
    __shared__ float t[32][33];
    int bx = blockIdx.x * 32;
    int by = blockIdx.y * 32;
    int x = threadIdx.x, y = threadIdx.y;
#pragma unroll
    for (int j = 0; j < 32; j += 8)
        t[y + j][x] = W[(size_t)(by + y + j) * Nc + bx + x];
    __syncthreads();
#pragma unroll
    for (int j = 0; j < 32; j += 8)
        Wt[perm_idx(bx + y + j, by + x)] = to_tf32(t[x][y + j]);
}

// =====================================================================
// x -> tf32 fragment layout
// =====================================================================
__global__ void permute_x(const float* __restrict__ x)
{
    int idx = blockIdx.x * 256 + threadIdx.x;
    int r = idx >> 7;
    int k = (idx & 127) * 4;
    float4 v = ((const float4*)x)[idx];
    size_t base = perm_idx(r, k);
    d_xr[base]      = to_tf32(v.x);
    d_xr[base + 4]  = to_tf32(v.y);
    d_xr[base + 8]  = to_tf32(v.z);
    d_xr[base + 12] = to_tf32(v.w);
}

// =====================================================================
// per-channel params
// =====================================================================
__global__ void prep_params(const float* __restrict__ scale_p,
                            const float* __restrict__ power_p)
{
    int c = threadIdx.x;
    d_scinv[c] = 1.f / log1pf(expf(scale_p[c]));
    d_pw[c] = 1.f + 4.f / (1.f + expf(-power_p[c]));
}

// =====================================================================
// features + fused km
// =====================================================================
__global__ __launch_bounds__(512)
void features_kernel(const float* __restrict__ pos_enc)
{
    int c   = threadIdx.x;
    int h   = c >> 6;
    int d   = c & 63;
    int bn0 = blockIdx.x * 16;
    int b   = bn0 / Nn;
    int n0  = bn0 - b * Nn;

    float scinv = d_scinv[c];
    float pw    = d_pw[c];
    float skp = 0.f, skn = 0.f;

#pragma unroll 4
    for (int i = 0; i < 16; i++) {
        int bn_ = bn0 + i;
        int n   = n0 + i;
        float qv  = d_qgkv[(size_t)bn_ * 2048 + c] * scinv;
        float kvv = (d_qgkv[(size_t)bn_ * 2048 + 1024 + c] + pos_enc[n * Cn + c]) * scinv;

        float qa = exp2f(pw * __log2f(fabsf(qv)));
        float ka = exp2f(pw * __log2f(fabsf(kvv)));
        float qp = (qv  > 0.f) ? qa : 0.f;
        float qn = (qv  < 0.f) ? qa : 0.f;
        float kp = (kvv > 0.f) ? ka : 0.f;
        float kn = (kvv < 0.f) ? ka : 0.f;

        size_t fbase = ((size_t)(b * NH + h) * Nn + n) * Fn;
        d_qf[fbase + d]      = __float2bfloat16_rn(qp);
        d_qf[fbase + 64 + d] = __float2bfloat16_rn(qn);
        d_kf[fbase + d]      = __float2bfloat16_rn(kp);
        d_kf[fbase + 64 + d] = __float2bfloat16_rn(kn);
        skp += kp; skn += kn;
    }
    const float inv_n = 1.f / (float)Nn;
    atomicAdd(&d_km[(b * NH + h) * Fn + d],      skp * inv_n);
    atomicAdd(&d_km[(b * NH + h) * Fn + 64 + d], skn * inv_n);
}

// =====================================================================
// zero km + kvm accumulators
// =====================================================================
__global__ void zero_aux_kernel()
{
    int i = blockIdx.x * blockDim.x + threadIdx.x;
    int stride = gridDim.x * blockDim.x;
    if (i < Bn * NH * Fn) d_km[i] = 0.f;
    for (int j = i; j < Bn * NH * Fn * 64; j += stride) d_kvm[j] = 0.f;
}

// =====================================================================
// kvm via mma
// =====================================================================
#define KV_SEG 1568

__global__ __launch_bounds__(256)
void kvm_mma()
{
    __shared__ __align__(16) uint16_t kfs[2][32][136];
    __shared__ __align__(16) float    vss[2][32][72];
    int bh = blockIdx.x, seg = blockIdx.y;
    int b = bh >> 3, h = bh & 7;
    int tid = threadIdx.x, wid = tid >> 5, lane = tid & 31;
    int lr = lane >> 2, lc = lane & 3;
    int wd = (wid & 1) * 64;
    int we = (wid >> 1) * 16;

    float c[4][2][4];
#pragma unroll
    for (int mt = 0; mt < 4; mt++)
#pragma unroll
        for (int nt = 0; nt < 2; nt++)
#pragma unroll
            for (int j = 0; j < 4; j++) c[mt][nt][j] = 0.f;

    int nbase = seg * KV_SEG;
#pragma unroll
    for (int j = 0; j < 2; j++) {
        int idx = tid + j * 256;
        int r = idx >> 4, cs = idx & 15;
        cp_async16(smem_u32(&kfs[0][r][cs * 8]),
                   &d_kf[((size_t)bh * Nn + nbase + r) * 128 + cs * 8]);
        cp_async16(smem_u32(&vss[0][r][cs * 4]),
                   &d_qgkv[((size_t)(b * Nn) + nbase + r) * 2048 + 1536 + h * 64 + cs * 4]);
    }
    CP_COMMIT();

    for (int t = 0; t < 49; t++) {
        if (t + 1 < 49) {
            int nb = (t + 1) & 1;
            int n0 = nbase + (t + 1) * 32;
#pragma unroll
            for (int j = 0; j < 2; j++) {
                int idx = tid + j * 256;
                int r = idx >> 4, cs = idx & 15;
                cp_async16(smem_u32(&kfs[nb][r][cs * 8]),
                           &d_kf[((size_t)bh * Nn + n0 + r) * 128 + cs * 8]);
                cp_async16(smem_u32(&vss[nb][r][cs * 4]),
                           &d_qgkv[((size_t)(b * Nn) + n0 + r) * 2048 + 1536 + h * 64 + cs * 4]);
            }
            CP_COMMIT();
            CP_WAIT(1);
        } else {
            CP_WAIT(0);
        }
        __syncthreads();
        int buf = t & 1;
#pragma unroll
        for (int kk = 0; kk < 4; kk++) {
            int k0 = kk * 8;
            uint32_t a[4][4];
#pragma unroll
            for (int mt = 0; mt < 4; mt++) {
                int db = wd + mt * 16;
                a[mt][0] = bf_as_tf32(kfs[buf][k0 + lc][db + lr]);
                a[mt][1] = bf_as_tf32(kfs[buf][k0 + lc][db + lr + 8]);
                a[mt][2] = bf_as_tf32(kfs[buf][k0 + lc + 4][db + lr]);
                a[mt][3] = bf_as_tf32(kfs[buf][k0 + lc + 4][db + lr + 8]);
            }
#pragma unroll
            for (int nt = 0; nt < 2; nt++) {
                int eb = we + nt * 8;
                uint32_t b0 = __float_as_uint(vss[buf][k0 + lc][eb + lr]);
                uint32_t b1 = __float_as_uint(vss[buf][k0 + lc + 4][eb + lr]);
#pragma unroll
                for (int mt = 0; mt < 4; mt++)
                    mma_tf32_16_8_8(c[mt][nt], a[mt], b0, b1);
            }
        }
        __syncthreads();
    }

    const float inv_n = 1.f / (float)Nn;
    float* dst = &d_kvm[(size_t)bh * 8192];
#pragma unroll
    for (int mt = 0; mt < 4; mt++) {
        int d0 = wd + mt * 16 + lr;
#pragma unroll
        for (int nt = 0; nt < 2; nt++) {
            int e0 = we + nt * 8 + 2 * lc;
            atomicAdd(&dst[d0 * 64 + e0],           c[mt][nt][0] * inv_n);
            atomicAdd(&dst[d0 * 64 + e0 + 1],       c[mt][nt][1] * inv_n);
            atomicAdd(&dst[(d0 + 8) * 64 + e0],     c[mt][nt][2] * inv_n);
            atomicAdd(&dst[(d0 + 8) * 64 + e0 + 1], c[mt][nt][3] * inv_n);
        }
    }
}

// =====================================================================
// build KVM2
// =====================================================================
__global__ void build_kvm2()
{
    int bh = blockIdx.x;
    const float* kvm = &d_kvm[(size_t)bh * 8192];
    const float* km  = &d_km[bh * 128];
    float* out = &d_kvm2[(size_t)bh * 9216];
    for (int i = threadIdx.x; i < 128 * 72; i += 256) {
        int dd = i / 72, col = i - dd * 72;
        float v;
        if (col < 32)       v = kvm[dd * 64 + col];
        else if (col < 64)  v = kvm[(dd ^ 64) * 64 + col];
        else if (col == 64) v = km[dd];
        else if (col == 65) v = km[dd ^ 64];
        else                v = 0.f;
        out[i] = v;
    }
}

// =====================================================================
// attention via mma; scatter-stores d_t in FRAGMENT layout
// =====================================================================
#define ATT_SMEM (36864 + 17408)

__global__ __launch_bounds__(128)
void attn_mma()
{
    extern __shared__ char smx[];
    float*    Bsm = (float*)smx;
    uint16_t* Asm = (uint16_t*)(smx + 36864);
    int m0 = blockIdx.x * 64, bh = blockIdx.y;
    int b = bh >> 3, h = bh & 7;
    int tid = threadIdx.x, wid = tid >> 5, lane = tid & 31;
    int lr = lane >> 2, lc = lane & 3;
    int wm = wid * 16;

    {
        const char* bsrc = (const char*)&d_kvm2[(size_t)bh * 9216];
#pragma unroll
        for (int j = 0; j < 18; j++) {
            int idx = tid + j * 128;
            cp_async16(smem_u32((char*)Bsm + idx * 16), bsrc + idx * 16);
        }
#pragma unroll
        for (int j = 0; j < 8; j++) {
            int idx = tid + j * 128;
            int r = idx >> 4, cs = idx & 15;
            cp_async16(smem_u32(&Asm[r * 136 + cs * 8]),
                       &d_qf[((size_t)bh * Nn + m0 + r) * 128 + cs * 8]);
        }
        CP_COMMIT(); CP_WAIT(0);
    }
    __syncthreads();

    float c[9][4];
#pragma unroll
    for (int nt = 0; nt < 9; nt++)
#pragma unroll
        for (int j = 0; j < 4; j++) c[nt][j] = 0.f;

#pragma unroll
    for (int kt = 0; kt < 16; kt++) {
        int k0 = kt * 8;
        uint32_t a[4];
        a[0] = bf_as_tf32(Asm[(wm + lr) * 136 + k0 + lc]);
        a[1] = bf_as_tf32(Asm[(wm + lr + 8) * 136 + k0 + lc]);
        a[2] = bf_as_tf32(Asm[(wm + lr) * 136 + k0 + lc + 4]);
        a[3] = bf_as_tf32(Asm[(wm + lr + 8) * 136 + k0 + lc + 4]);
#pragma unroll
        for (int nt = 0; nt < 9; nt++) {
            uint32_t b0 = __float_as_uint(Bsm[(k0 + lc) * 72 + nt * 8 + lr]);
            uint32_t b1 = __float_as_uint(Bsm[(k0 + lc + 4) * 72 + nt * 8 + lr]);
            mma_tf32_16_8_8(c[nt], a, b0, b1);
        }
    }

    int src = lane & 28;
    float den1a = __shfl_sync(0xffffffffu, c[8][0], src);
    float den2a = __shfl_sync(0xffffffffu, c[8][1], src);
    float den1b = __shfl_sync(0xffffffffu, c[8][2], src);
    float den2b = __shfl_sync(0xffffffffu, c[8][3], src);
    float z1a = 1.f / (den1a + 1e-6f), z2a = 1.f / (den2a + 1e-6f);
    float z1b = 1.f / (den1b + 1e-6f), z2b = 1.f / (den2b + 1e-6f);

    int ra = b * Nn + m0 + wm + lr;
    int rb = ra + 8;
#pragma unroll
    for (int nt = 0; nt < 8; nt++) {
        int col = nt * 8 + 2 * lc;
        float za = (col < 32) ? z1a : z2a;
        float zb = (col < 32) ? z1b : z2b;
        int k = h * 64 + col;
        d_t[perm_idx(ra, k)]     = c[nt][0] * za;
        d_t[perm_idx(ra, k + 1)] = c[nt][1] * za;
        d_t[perm_idx(rb, k)]     = c[nt][2] * zb;
        d_t[perm_idx(rb, k + 1)] = c[nt][3] * zb;
    }
}

// =====================================================================
// depthwise conv + gate; d_t accessed via fragment indices, stores tf32
// =====================================================================
__global__ __launch_bounds__(512)
void conv_gate_kernel(const float* __restrict__ dwc_w,
                      const float* __restrict__ dwc_b)
{
    __shared__ float ws[64 * 25];
    __shared__ float bs[64];
    int y = blockIdx.x;
    int b = blockIdx.y;
    int c = threadIdx.x;
    int d = c & 63;
    for (int i = c; i < 64 * 25; i += 512) ws[i] = dwc_w[i];
    if (c < 64) bs[c] = dwc_b[c];
    __syncthreads();

    const float* vbase = &d_qgkv[(size_t)(b * Nn) * 2048 + 1536 + c];

    float win[5][5];
#pragma unroll
    for (int dy = 0; dy < 5; dy++) {
        int yy = y + dy - 2;
        bool yok = (unsigned)yy < HW;
#pragma unroll
        for (int j = 0; j < 5; j++) {
            int xx = j - 2;
            win[dy][j] = (yok && (unsigned)xx < HW)
                         ? vbase[(size_t)(yy * HW + xx) * 2048] : 0.f;
        }
    }

    for (int x = 0; x < HW; x++) {
        float acc = bs[d];
#pragma unroll
        for (int dy = 0; dy < 5; dy++)
#pragma unroll
            for (int j = 0; j < 5; j++)
                acc = fmaf(win[dy][j], ws[d * 25 + dy * 5 + j], acc);

        int i1 = b * Nn + y * HW + x;
        float g = d_qgkv[(size_t)i1 * 2048 + 512 + c];
        size_t pi = perm_idx(i1, c);
        d_t[pi] = to_tf32((d_t[pi] + acc) * g);

        int xx = x + 3;
        bool xok = xx < HW;
#pragma unroll
        for (int dy = 0; dy < 5; dy++) {
#pragma unroll
            for (int j = 0; j < 4; j++) win[dy][j] = win[dy][j + 1];
            int yy = y + dy - 2;
            win[dy][4] = (xok && (unsigned)yy < HW)
                         ? vbase[(size_t)(yy * HW + xx) * 2048] : 0.f;
        }
    }
}

// =====================================================================
// launch (launch #3 == big gemm for ncu capture)
// =====================================================================
extern "C" void kernel_launch(void* const* d_in, const int* in_sizes, int n_in,
                              void* d_out, int out_size)
{
    const float* x       = (const float*)d_in[0];
    const float* qg_w    = (const float*)d_in[1];
    const float* kv_w    = (const float*)d_in[2];
    const float* proj_w  = (const float*)d_in[3];
    const float* proj_b  = (const float*)d_in[4];
    const float* pos_enc = (const float*)d_in[5];
    const float* scale_p = (const float*)d_in[6];
    const float* power_p = (const float*)d_in[7];
    const float* dwc_w   = (const float*)d_in[8];
    const float* dwc_b   = (const float*)d_in[9];
    float* out = (float*)d_out;

    float *p_qgkv, *p_t, *p_wtc, *p_wt3, *p_xr;
    cudaGetSymbolAddress((void**)&p_qgkv, d_qgkv);
    cudaGetSymbolAddress((void**)&p_t,    d_t);
    cudaGetSymbolAddress((void**)&p_wtc,  d_wtc);
    cudaGetSymbolAddress((void**)&p_wt3,  d_wt3);
    cudaGetSymbolAddress((void**)&p_xr,   d_xr);

    cudaFuncSetAttribute(gemm_mma, cudaFuncAttributeMaxDynamicSharedMemorySize,
                         GEMM_SMEM);
    cudaFuncSetAttribute(attn_mma, cudaFuncAttributeMaxDynamicSharedMemorySize,
                         ATT_SMEM);

    dim3 tb(32, 8);
    prep_params<<<1, 512>>>(scale_p, power_p);                       // 0
    permute_x<<<Mrows * 128 / 256, 256>>>(x);                        // 1
    transpose_qgkv<<<dim3(64, 16), tb>>>(qg_w, kv_w);                // 2
    gemm_mma<<<dim3(16, Mrows / 128), 256, GEMM_SMEM>>>(             // 3 (profiled)
        p_xr, p_wtc, nullptr, p_qgkv, 2048);
    transpose_w<<<dim3(16, 16), tb>>>(proj_w, p_wt3, 512);           // 4
    zero_aux_kernel<<<1024, 256>>>();                                // 5
    features_kernel<<<Mrows / 16, 512>>>(pos_enc);                   // 6
    kvm_mma<<<dim3(Bn * NH, 2), 256>>>();                            // 7
    build_kvm2<<<Bn * NH, 256>>>();                                  // 8
    attn_mma<<<dim3(Nn / 64, Bn * NH), 128, ATT_SMEM>>>();           // 9
    conv_gate_kernel<<<dim3(HW, Bn), 512>>>(dwc_w, dwc_b);           // 10
    gemm_mma<<<dim3(4, Mrows / 128), 256, GEMM_SMEM>>>(              // 11
        p_t, p_wt3, proj_b, out, 512);
}

// round 10
// speedup vs baseline: 1.0453x; 1.0047x over previous
#include <cuda_runtime.h>
#include <cuda_bf16.h>
#include <math.h>
#include <stdint.h>

// ---------------- problem constants ----------------
#define Bn   16
#define Nn   3136        // 56*56
#define Cn   512
#define NH   8
#define HD   64
#define Fn   128         // 2*HD
#define Mrows (Bn*Nn)    // 50176
#define HW   56

// ---------------- scratch (device globals; no allocs allowed) --------------
__device__ __align__(16) float d_qgkv[Mrows * 2048];        // [b,n, q|g|k|v] (512 each)
__device__ __align__(16) float d_xr[Mrows * 512];           // x, tf32, FRAGMENT layout
__device__ __align__(16) __nv_bfloat16 d_qf[Bn*NH*Nn*Fn];   // q_sim  [bh,n,128] bf16
__device__ __align__(16) __nv_bfloat16 d_kf[Bn*NH*Nn*Fn];   // kf     [bh,n,128] bf16
__device__ __align__(16) float d_km[Bn*NH*Fn];              // mean over n
__device__ __align__(16) float d_kvm[Bn*NH*Fn*64];          // [bh,d(128),e(64)]
__device__ __align__(16) float d_kvm2[Bn*NH*Fn*72];         // [bh,d(128),72] B for attn
__device__ __align__(16) float d_t [Mrows * Cn];            // (xo+vd)*g, tf32, FRAGMENT layout
__device__ __align__(16) float d_wtc[2048 * 512];           // [qg_w|kv_w]^T tf32, FRAGMENT
__device__ __align__(16) float d_wt3[512 * 512];            // proj_w^T tf32, FRAGMENT
__device__ __align__(16) float d_scinv[Cn];
__device__ __align__(16) float d_pw[Cn];

// =====================================================================
// helpers (baseline PTX only)
// =====================================================================
__device__ __forceinline__ uint32_t smem_u32(const void* p) {
    uint32_t a;
    asm("{ .reg .u64 t; cvta.to.shared.u64 t, %1; cvt.u32.u64 %0, t; }"
        : "=r"(a) : "l"(p));
    return a;
}

__device__ __forceinline__ float to_tf32(float x) {
    float r;
    asm("cvt.rna.tf32.f32 %0, %1;" : "=f"(r) : "f"(x));
    return r;
}

__device__ __forceinline__ void cp_async16(uint32_t saddr, const void* gaddr) {
    asm volatile("cp.async.ca.shared.global [%0], [%1], 16;"
                 :: "r"(saddr), "l"(gaddr) : "memory");
}
#define CP_COMMIT() asm volatile("cp.async.commit_group;" ::: "memory")
#define CP_WAIT(N)  asm volatile("cp.async.wait_group %0;" :: "n"(N) : "memory")

__device__ __forceinline__ void mma_tf32_16_8_8(float* c, const uint32_t* a,
                                                uint32_t b0, uint32_t b1) {
    asm volatile(
        "mma.sync.aligned.m16n8k8.row.col.f32.tf32.tf32.f32 "
        "{%0,%1,%2,%3}, {%4,%5,%6,%7}, {%8,%9}, {%0,%1,%2,%3};"
        : "+f"(c[0]), "+f"(c[1]), "+f"(c[2]), "+f"(c[3])
        : "r"(a[0]), "r"(a[1]), "r"(a[2]), "r"(a[3]), "r"(b0), "r"(b1));
}

__device__ __forceinline__ uint32_t bf_as_tf32(uint16_t h) {
    __nv_bfloat16 b = *reinterpret_cast<__nv_bfloat16*>(&h);
    return __float_as_uint(__bfloat162float(b));
}

// fragment-order permutation for K=512 operand panels of 128 rows.
__device__ __forceinline__ size_t perm_idx(int r, int k) {
    return (size_t)(r >> 7) * 65536
         + (size_t)((((k >> 3) * 8 + ((r >> 4) & 7)) << 7)
         + (((r & 7) * 4 + (k & 3)) << 2)
         + ((r >> 3) & 1) + (((k >> 2) & 1) << 1));
}

// =====================================================================
// tensor-core tf32 GEMM: C[M,Nc] = A[M,512] @ Bt[Nc,512]^T (+bias)
// A, Bt in FRAGMENT layout. CTA 128x128, 4 warps (2m x 2n), warp 64x64.
// 2 CTAs/SM, 3-stage cp.async, 1 barrier/k-tile.
// Crossbar: 64KB per k-tile per CTA (minimum for this CTA shape).
// =====================================================================
#define GEMM_SMEM (3 * 8192 * 4)       // 3 stages x 32KB = 98304 B

__global__ __launch_bounds__(128, 2)
void gemm_mma(const float* __restrict__ A, const float* __restrict__ Bt,
              const float* __restrict__ bias, float* __restrict__ Cm, int Nc)
{
    extern __shared__ float sm[];
    float* stage[3] = { sm, sm + 8192, sm + 16384 };
    const int tid = threadIdx.x;
    const int bn_panel = blockIdx.x;
    const int bm_panel = blockIdx.y;
    const int wid = tid >> 5, lane = tid & 31;
    const int lr = lane >> 2, lc = lane & 3;
    const int wmg = (wid & 1) * 4;       // A 16-row-group base (0 or 4)
    const int wng = (wid >> 1) * 4;      // B 16-col-group base (0 or 4)

    const float* Ab = A  + (size_t)bm_panel * 65536;
    const float* Bb = Bt + (size_t)bn_panel * 65536;

    float c[4][8][4];
#pragma unroll
    for (int mt = 0; mt < 4; mt++)
#pragma unroll
        for (int nt = 0; nt < 8; nt++)
#pragma unroll
            for (int j = 0; j < 4; j++) c[mt][nt][j] = 0.f;

    auto issue_stage = [&](int buf, int t) {
        uint32_t sa = smem_u32(stage[buf]);
        const float* as = Ab + t * 4096;
        const float* bs = Bb + t * 4096;
#pragma unroll
        for (int i = 0; i < 8; i++) {
            int ch = tid + i * 128;
            cp_async16(sa + ch * 16, as + ch * 4);
        }
#pragma unroll
        for (int i = 0; i < 8; i++) {
            int ch = tid + i * 128;
            cp_async16(sa + 16384 + ch * 16, bs + ch * 4);
        }
        CP_COMMIT();
    };

    issue_stage(0, 0);
    issue_stage(1, 1);

    for (int t = 0; t < 16; t++) {
        CP_WAIT(1);
        __syncthreads();
        if (t + 2 < 16) issue_stage((t + 2) % 3, t + 2);
        else            CP_COMMIT();

        const float4* sa4 = (const float4*)stage[t % 3];
        const float4* sb4 = (const float4*)(stage[t % 3] + 4096);
#pragma unroll
        for (int kk = 0; kk < 4; kk++) {
            uint32_t a[4][4];
            float4 bv[4];
#pragma unroll
            for (int mt = 0; mt < 4; mt++) {
                float4 v = sa4[(kk * 8 + wmg + mt) * 32 + lane];
                a[mt][0] = __float_as_uint(v.x);
                a[mt][1] = __float_as_uint(v.y);
                a[mt][2] = __float_as_uint(v.z);
                a[mt][3] = __float_as_uint(v.w);
            }
#pragma unroll
            for (int p = 0; p < 4; p++)
                bv[p] = sb4[(kk * 8 + wng + p) * 32 + lane];
#pragma unroll
            for (int mt = 0; mt < 4; mt++)
#pragma unroll
                for (int p = 0; p < 4; p++) {
                    mma_tf32_16_8_8(c[mt][2 * p],
                                    a[mt], __float_as_uint(bv[p].x),
                                           __float_as_uint(bv[p].z));
                    mma_tf32_16_8_8(c[mt][2 * p + 1],
                                    a[mt], __float_as_uint(bv[p].y),
                                           __float_as_uint(bv[p].w));
                }
        }
    }

#pragma unroll
    for (int mt = 0; mt < 4; mt++) {
        int row = bm_panel * 128 + (wid & 1) * 64 + mt * 16 + lr;
#pragma unroll
        for (int nt = 0; nt < 8; nt++) {
            int col = bn_panel * 128 + (wid >> 1) * 64 + nt * 8 + lc * 2;
            float2 v0 = make_float2(c[mt][nt][0], c[mt][nt][1]);
            float2 v1 = make_float2(c[mt][nt][2], c[mt][nt][3]);
            if (bias) {
                float b0 = bias[col], b1 = bias[col + 1];
                v0.x += b0; v0.y += b1;
                v1.x += b0; v1.y += b1;
            }
            *(float2*)&Cm[(size_t)row * Nc + col] = v0;
            *(float2*)&Cm[(size_t)(row + 8) * Nc + col] = v1;
        }
    }
}

// =====================================================================
// weight transposes -> fragment layout, tf32
// =====================================================================
__global__ void transpose_qgkv(const float* __restrict__ qg_w,
                               const float* __restrict__ kv_w)
{
    __shared__ float t[32][33];
    int bx = blockIdx.x * 32;
    int by = blockIdx.y * 32;
    int x = threadIdx.x, y = threadIdx.y;
    const float* W = (bx < 1024) ? qg_w : kv_w;
    int nb = bx & 1023;
#pragma unroll
    for (int j = 0; j < 32; j += 8)
        t[y + j][x] = W[(size_t)(by + y + j) * 1024 + nb + x];
    __syncthreads();
#pragma unroll
    for (int j = 0; j < 32; j += 8)
        d_wtc[perm_idx(bx + y + j, by + x)] = to_tf32(t[x][y + j]);
}

__global__ void transpose_w(const float* __restrict__ W, float* __restrict__ Wt, int Nc)
{
    __shared__ float t[32][33];
    int bx = blockIdx.x * 32;
    int by = blockIdx.y * 32;
    int x = threadIdx.x, y = threadIdx.y;
#pragma unroll
    for (int j = 0; j < 32; j += 8)
        t[y + j][x] = W[(size_t)(by + y + j) * Nc + bx + x];
    __syncthreads();
#pragma unroll
    for (int j = 0; j < 32; j += 8)
        Wt[perm_idx(bx + y + j, by + x)] = to_tf32(t[x][y + j]);
}

// =====================================================================
// x -> tf32 fragment layout
// =====================================================================
__global__ void permute_x(const float* __restrict__ x)
{
    int idx = blockIdx.x * 256 + threadIdx.x;
    int r = idx >> 7;
    int k = (idx & 127) * 4;
    float4 v = ((const float4*)x)[idx];
    size_t base = perm_idx(r, k);
    d_xr[base]      = to_tf32(v.x);
    d_xr[base + 4]  = to_tf32(v.y);
    d_xr[base + 8]  = to_tf32(v.z);
    d_xr[base + 12] = to_tf32(v.w);
}

// =====================================================================
// per-channel params
// =====================================================================
__global__ void prep_params(const float* __restrict__ scale_p,
                            const float* __restrict__ power_p)
{
    int c = threadIdx.x;
    d_scinv[c] = 1.f / log1pf(expf(scale_p[c]));
    d_pw[c] = 1.f + 4.f / (1.f + expf(-power_p[c]));
}

// =====================================================================
// features + fused km
// =====================================================================
__global__ __launch_bounds__(512)
void features_kernel(const float* __restrict__ pos_enc)
{
    int c   = threadIdx.x;
    int h   = c >> 6;
    int d   = c & 63;
    int bn0 = blockIdx.x * 16;
    int b   = bn0 / Nn;
    int n0  = bn0 - b * Nn;

    float scinv = d_scinv[c];
    float pw    = d_pw[c];
    float skp = 0.f, skn = 0.f;

#pragma unroll 4
    for (int i = 0; i < 16; i++) {
        int bn_ = bn0 + i;
        int n   = n0 + i;
        float qv  = d_qgkv[(size_t)bn_ * 2048 + c] * scinv;
        float kvv = (d_qgkv[(size_t)bn_ * 2048 + 1024 + c] + pos_enc[n * Cn + c]) * scinv;

        float qa = exp2f(pw * __log2f(fabsf(qv)));
        float ka = exp2f(pw * __log2f(fabsf(kvv)));
        float qp = (qv  > 0.f) ? qa : 0.f;
        float qn = (qv  < 0.f) ? qa : 0.f;
        float kp = (kvv > 0.f) ? ka : 0.f;
        float kn = (kvv < 0.f) ? ka : 0.f;

        size_t fbase = ((size_t)(b * NH + h) * Nn + n) * Fn;
        d_qf[fbase + d]      = __float2bfloat16_rn(qp);
        d_qf[fbase + 64 + d] = __float2bfloat16_rn(qn);
        d_kf[fbase + d]      = __float2bfloat16_rn(kp);
        d_kf[fbase + 64 + d] = __float2bfloat16_rn(kn);
        skp += kp; skn += kn;
    }
    const float inv_n = 1.f / (float)Nn;
    atomicAdd(&d_km[(b * NH + h) * Fn + d],      skp * inv_n);
    atomicAdd(&d_km[(b * NH + h) * Fn + 64 + d], skn * inv_n);
}

// =====================================================================
// zero km + kvm accumulators
// =====================================================================
__global__ void zero_aux_kernel()
{
    int i = blockIdx.x * blockDim.x + threadIdx.x;
    int stride = gridDim.x * blockDim.x;
    if (i < Bn * NH * Fn) d_km[i] = 0.f;
    for (int j = i; j < Bn * NH * Fn * 64; j += stride) d_kvm[j] = 0.f;
}

// =====================================================================
// kvm via mma (4 segments for better SM balance)
// =====================================================================
#define KV_SEG 784

__global__ __launch_bounds__(256)
void kvm_mma()
{
    __shared__ __align__(16) uint16_t kfs[2][32][136];
    __shared__ __align__(16) float    vss[2][32][72];
    int bh = blockIdx.x, seg = blockIdx.y;
    int b = bh >> 3, h = bh & 7;
    int tid = threadIdx.x, wid = tid >> 5, lane = tid & 31;
    int lr = lane >> 2, lc = lane & 3;
    int wd = (wid & 1) * 64;
    int we = (wid >> 1) * 16;

    float c[4][2][4];
#pragma unroll
    for (int mt = 0; mt < 4; mt++)
#pragma unroll
        for (int nt = 0; nt < 2; nt++)
#pragma unroll
            for (int j = 0; j < 4; j++) c[mt][nt][j] = 0.f;

    int nbase = seg * KV_SEG;
    const int NIT = KV_SEG / 32;    // 24.5 -> 784/32 = 24.5? 784 = 24*32 + 16
    // 784 = 32*24 + 16; handle with 25 iterations, last partial guarded by range
#pragma unroll
    for (int j = 0; j < 2; j++) {
        int idx = tid + j * 256;
        int r = idx >> 4, cs = idx & 15;
        cp_async16(smem_u32(&kfs[0][r][cs * 8]),
                   &d_kf[((size_t)bh * Nn + nbase + r) * 128 + cs * 8]);
        cp_async16(smem_u32(&vss[0][r][cs * 4]),
                   &d_qgkv[((size_t)(b * Nn) + nbase + r) * 2048 + 1536 + h * 64 + cs * 4]);
    }
    CP_COMMIT();

    // 784 rows per segment: 24 full 32-row tiles + one 16-row tail tile.
    const int NT = 25;
    for (int t = 0; t < NT; t++) {
        if (t + 1 < NT) {
            int nb = (t + 1) & 1;
            int n0 = nbase + (t + 1) * 32;
            int rows = (t + 1 == NT - 1) ? 16 : 32;
#pragma unroll
            for (int j = 0; j < 2; j++) {
                int idx = tid + j * 256;
                int r = idx >> 4, cs = idx & 15;
                if (r < rows) {
                    cp_async16(smem_u32(&kfs[nb][r][cs * 8]),
                               &d_kf[((size_t)bh * Nn + n0 + r) * 128 + cs * 8]);
                    cp_async16(smem_u32(&vss[nb][r][cs * 4]),
                               &d_qgkv[((size_t)(b * Nn) + n0 + r) * 2048 + 1536 + h * 64 + cs * 4]);
                } else {
                    // zero-fill tail rows so the mma contributes nothing
                    *(float4*)((char*)&kfs[nb][r][cs * 8]) = make_float4(0.f, 0.f, 0.f, 0.f);
                    *(float4*)&vss[nb][r][cs * 4] = make_float4(0.f, 0.f, 0.f, 0.f);
                }
            }
            CP_COMMIT();
            CP_WAIT(1);
        } else {
            CP_WAIT(0);
        }
        __syncthreads();
        int buf = t & 1;
#pragma unroll
        for (int kk = 0; kk < 4; kk++) {
            int k0 = kk * 8;
            uint32_t a[4][4];
#pragma unroll
            for (int mt = 0; mt < 4; mt++) {
                int db = wd + mt * 16;
                a[mt][0] = bf_as_tf32(kfs[buf][k0 + lc][db + lr]);
                a[mt][1] = bf_as_tf32(kfs[buf][k0 + lc][db + lr + 8]);
                a[mt][2] = bf_as_tf32(kfs[buf][k0 + lc + 4][db + lr]);
                a[mt][3] = bf_as_tf32(kfs[buf][k0 + lc + 4][db + lr + 8]);
            }
#pragma unroll
            for (int nt = 0; nt < 2; nt++) {
                int eb = we + nt * 8;
                uint32_t b0 = __float_as_uint(vss[buf][k0 + lc][eb + lr]);
                uint32_t b1 = __float_as_uint(vss[buf][k0 + lc + 4][eb + lr]);
#pragma unroll
                for (int mt = 0; mt < 4; mt++)
                    mma_tf32_16_8_8(c[mt][nt], a[mt], b0, b1);
            }
        }
        __syncthreads();
    }

    const float inv_n = 1.f / (float)Nn;
    float* dst = &d_kvm[(size_t)bh * 8192];
#pragma unroll
    for (int mt = 0; mt < 4; mt++) {
        int d0 = wd + mt * 16 + lr;
#pragma unroll
        for (int nt = 0; nt < 2; nt++) {
            int e0 = we + nt * 8 + 2 * lc;
            atomicAdd(&dst[d0 * 64 + e0],           c[mt][nt][0] * inv_n);
            atomicAdd(&dst[d0 * 64 + e0 + 1],       c[mt][nt][1] * inv_n);
            atomicAdd(&dst[(d0 + 8) * 64 + e0],     c[mt][nt][2] * inv_n);
            atomicAdd(&dst[(d0 + 8) * 64 + e0 + 1], c[mt][nt][3] * inv_n);
        }
    }
}

// =====================================================================
// build KVM2
// =====================================================================
__global__ void build_kvm2()
{
    int bh = blockIdx.x;
    const float* kvm = &d_kvm[(size_t)bh * 8192];
    const float* km  = &d_km[bh * 128];
    float* out = &d_kvm2[(size_t)bh * 9216];
    for (int i = threadIdx.x; i < 128 * 72; i += 256) {
        int dd = i / 72, col = i - dd * 72;
        float v;
        if (col < 32)       v = kvm[dd * 64 + col];
        else if (col < 64)  v = kvm[(dd ^ 64) * 64 + col];
        else if (col == 64) v = km[dd];
        else if (col == 65) v = km[dd ^ 64];
        else                v = 0.f;
        out[i] = v;
    }
}

// =====================================================================
// attention via mma; scatter-stores d_t in FRAGMENT layout
// =====================================================================
#define ATT_SMEM (36864 + 17408)

__global__ __launch_bounds__(128)
void attn_mma()
{
    extern __shared__ char smx[];
    float*    Bsm = (float*)smx;
    uint16_t* Asm = (uint16_t*)(smx + 36864);
    int m0 = blockIdx.x * 64, bh = blockIdx.y;
    int b = bh >> 3, h = bh & 7;
    int tid = threadIdx.x, wid = tid >> 5, lane = tid & 31;
    int lr = lane >> 2, lc = lane & 3;
    int wm = wid * 16;

    {
        const char* bsrc = (const char*)&d_kvm2[(size_t)bh * 9216];
#pragma unroll
        for (int j = 0; j < 18; j++) {
            int idx = tid + j * 128;
            cp_async16(smem_u32((char*)Bsm + idx * 16), bsrc + idx * 16);
        }
#pragma unroll
        for (int j = 0; j < 8; j++) {
            int idx = tid + j * 128;
            int r = idx >> 4, cs = idx & 15;
            cp_async16(smem_u32(&Asm[r * 136 + cs * 8]),
                       &d_qf[((size_t)bh * Nn + m0 + r) * 128 + cs * 8]);
        }
        CP_COMMIT(); CP_WAIT(0);
    }
    __syncthreads();

    float c[9][4];
#pragma unroll
    for (int nt = 0; nt < 9; nt++)
#pragma unroll
        for (int j = 0; j < 4; j++) c[nt][j] = 0.f;

#pragma unroll
    for (int kt = 0; kt < 16; kt++) {
        int k0 = kt * 8;
        uint32_t a[4];
        a[0] = bf_as_tf32(Asm[(wm + lr) * 136 + k0 + lc]);
        a[1] = bf_as_tf32(Asm[(wm + lr + 8) * 136 + k0 + lc]);
        a[2] = bf_as_tf32(Asm[(wm + lr) * 136 + k0 + lc + 4]);
        a[3] = bf_as_tf32(Asm[(wm + lr + 8) * 136 + k0 + lc + 4]);
#pragma unroll
        for (int nt = 0; nt < 9; nt++) {
            uint32_t b0 = __float_as_uint(Bsm[(k0 + lc) * 72 + nt * 8 + lr]);
            uint32_t b1 = __float_as_uint(Bsm[(k0 + lc + 4) * 72 + nt * 8 + lr]);
            mma_tf32_16_8_8(c[nt], a, b0, b1);
        }
    }

    int src = lane & 28;
    float den1a = __shfl_sync(0xffffffffu, c[8][0], src);
    float den2a = __shfl_sync(0xffffffffu, c[8][1], src);
    float den1b = __shfl_sync(0xffffffffu, c[8][2], src);
    float den2b = __shfl_sync(0xffffffffu, c[8][3], src);
    float z1a = 1.f / (den1a + 1e-6f), z2a = 1.f / (den2a + 1e-6f);
    float z1b = 1.f / (den1b + 1e-6f), z2b = 1.f / (den2b + 1e-6f);

    int ra = b * Nn + m0 + wm + lr;
    int rb = ra + 8;
#pragma unroll
    for (int nt = 0; nt < 8; nt++) {
        int col = nt * 8 + 2 * lc;
        float za = (col < 32) ? z1a : z2a;
        float zb = (col < 32) ? z1b : z2b;
        int k = h * 64 + col;
        d_t[perm_idx(ra, k)]     = c[nt][0] * za;
        d_t[perm_idx(ra, k + 1)] = c[nt][1] * za;
        d_t[perm_idx(rb, k)]     = c[nt][2] * zb;
        d_t[perm_idx(rb, k + 1)] = c[nt][3] * zb;
    }
}

// =====================================================================
// depthwise conv + gate; d_t accessed via fragment indices, stores tf32
// =====================================================================
__global__ __launch_bounds__(512)
void conv_gate_kernel(const float* __restrict__ dwc_w,
                      const float* __restrict__ dwc_b)
{
    __shared__ float ws[64 * 25];
    __shared__ float bs[64];
    int y = blockIdx.x;
    int b = blockIdx.y;
    int c = threadIdx.x;
    int d = c & 63;
    for (int i = c; i < 64 * 25; i += 512) ws[i] = dwc_w[i];
    if (c < 64) bs[c] = dwc_b[c];
    __syncthreads();

    const float* vbase = &d_qgkv[(size_t)(b * Nn) * 2048 + 1536 + c];

    float win[5][5];
#pragma unroll
    for (int dy = 0; dy < 5; dy++) {
        int yy = y + dy - 2;
        bool yok = (unsigned)yy < HW;
#pragma unroll
        for (int j = 0; j < 5; j++) {
            int xx = j - 2;
            win[dy][j] = (yok && (unsigned)xx < HW)
                         ? vbase[(size_t)(yy * HW + xx) * 2048] : 0.f;
        }
    }

    for (int x = 0; x < HW; x++) {
        float acc = bs[d];
#pragma unroll
        for (int dy = 0; dy < 5; dy++)
#pragma unroll
            for (int j = 0; j < 5; j++)
                acc = fmaf(win[dy][j], ws[d * 25 + dy * 5 + j], acc);

        int i1 = b * Nn + y * HW + x;
        float g = d_qgkv[(size_t)i1 * 2048 + 512 + c];
        size_t pi = perm_idx(i1, c);
        d_t[pi] = to_tf32((d_t[pi] + acc) * g);

        int xx = x + 3;
        bool xok = xx < HW;
#pragma unroll
        for (int dy = 0; dy < 5; dy++) {
#pragma unroll
            for (int j = 0; j < 4; j++) win[dy][j] = win[dy][j + 1];
            int yy = y + dy - 2;
            win[dy][4] = (xok && (unsigned)yy < HW)
                         ? vbase[(size_t)(yy * HW + xx) * 2048] : 0.f;
        }
    }
}

// =====================================================================
// launch (launch #3 == big gemm for ncu capture)
// =====================================================================
extern "C" void kernel_launch(void* const* d_in, const int* in_sizes, int n_in,
                              void* d_out, int out_size)
{
    const float* x       = (const float*)d_in[0];
    const float* qg_w    = (const float*)d_in[1];
    const float* kv_w    = (const float*)d_in[2];
    const float* proj_w  = (const float*)d_in[3];
    const float* proj_b  = (const float*)d_in[4];
    const float* pos_enc = (const float*)d_in[5];
    const float* scale_p = (const float*)d_in[6];
    const float* power_p = (const float*)d_in[7];
    const float* dwc_w   = (const float*)d_in[8];
    const float* dwc_b   = (const float*)d_in[9];
    float* out = (float*)d_out;

    float *p_qgkv, *p_t, *p_wtc, *p_wt3, *p_xr;
    cudaGetSymbolAddress((void**)&p_qgkv, d_qgkv);
    cudaGetSymbolAddress((void**)&p_t,    d_t);
    cudaGetSymbolAddress((void**)&p_wtc,  d_wtc);
    cudaGetSymbolAddress((void**)&p_wt3,  d_wt3);
    cudaGetSymbolAddress((void**)&p_xr,   d_xr);

    cudaFuncSetAttribute(gemm_mma, cudaFuncAttributeMaxDynamicSharedMemorySize,
                         GEMM_SMEM);
    cudaFuncSetAttribute(attn_mma, cudaFuncAttributeMaxDynamicSharedMemorySize,
                         ATT_SMEM);

    dim3 tb(32, 8);
    prep_params<<<1, 512>>>(scale_p, power_p);                       // 0
    permute_x<<<Mrows * 128 / 256, 256>>>(x);                        // 1
    transpose_qgkv<<<dim3(64, 16), tb>>>(qg_w, kv_w);                // 2
    gemm_mma<<<dim3(16, Mrows / 128), 128, GEMM_SMEM>>>(             // 3 (profiled)
        p_xr, p_wtc, nullptr, p_qgkv, 2048);
    transpose_w<<<dim3(16, 16), tb>>>(proj_w, p_wt3, 512);           // 4
    zero_aux_kernel<<<1024, 256>>>();                                // 5
    features_kernel<<<Mrows / 16, 512>>>(pos_enc);                   // 6
    kvm_mma<<<dim3(Bn * NH, 4), 256>>>();                            // 7
    build_kvm2<<<Bn * NH, 256>>>();                                  // 8
    attn_mma<<<dim3(Nn / 64, Bn * NH), 128, ATT_SMEM>>>();           // 9
    conv_gate_kernel<<<dim3(HW, Bn), 512>>>(dwc_w, dwc_b);           // 10
    gemm_mma<<<dim3(4, Mrows / 128), 128, GEMM_SMEM>>>(              // 11
        p_t, p_wt3, proj_b, out, 512);
}

// round 11
// speedup vs baseline: 1.0458x; 1.0005x over previous
#include <cuda_runtime.h>
#include <cuda_bf16.h>
#include <math.h>
#include <stdint.h>

// ---------------- problem constants ----------------
#define Bn   16
#define Nn   3136        // 56*56
#define Cn   512
#define NH   8
#define HD   64
#define Fn   128         // 2*HD
#define Mrows (Bn*Nn)    // 50176
#define HW   56

// ---------------- scratch (device globals; no allocs allowed) --------------
__device__ __align__(16) float d_qgkv[Mrows * 2048];        // [b,n, q|g|k|v] (512 each)
__device__ __align__(16) float d_xr[Mrows * 512];           // x, tf32, FRAGMENT layout
__device__ __align__(16) __nv_bfloat16 d_qf[Bn*NH*Nn*Fn];   // q_sim  [bh,n,128] bf16
__device__ __align__(16) __nv_bfloat16 d_kf[Bn*NH*Nn*Fn];   // kf     [bh,n,128] bf16
__device__ __align__(16) float d_km[Bn*NH*Fn];              // mean over n
__device__ __align__(16) float d_kvm[Bn*NH*Fn*64];          // [bh,d(128),e(64)]
__device__ __align__(16) float d_kvm2[Bn*NH*Fn*72];         // [bh,d(128),72] B for attn
__device__ __align__(16) float d_t [Mrows * Cn];            // (xo+vd)*g, tf32, FRAGMENT layout
__device__ __align__(16) float d_wtc[2048 * 512];           // [qg_w|kv_w]^T tf32, FRAGMENT
__device__ __align__(16) float d_wt3[512 * 512];            // proj_w^T tf32, FRAGMENT
__device__ __align__(16) float d_scinv[Cn];
__device__ __align__(16) float d_pw[Cn];

// =====================================================================
// helpers (baseline PTX only)
// =====================================================================
__device__ __forceinline__ uint32_t smem_u32(const void* p) {
    uint32_t a;
    asm("{ .reg .u64 t; cvta.to.shared.u64 t, %1; cvt.u32.u64 %0, t; }"
        : "=r"(a) : "l"(p));
    return a;
}

__device__ __forceinline__ float to_tf32(float x) {
    float r;
    asm("cvt.rna.tf32.f32 %0, %1;" : "=f"(r) : "f"(x));
    return r;
}

__device__ __forceinline__ void cp_async16(uint32_t saddr, const void* gaddr) {
    asm volatile("cp.async.ca.shared.global [%0], [%1], 16;"
                 :: "r"(saddr), "l"(gaddr) : "memory");
}
#define CP_COMMIT() asm volatile("cp.async.commit_group;" ::: "memory")
#define CP_WAIT(N)  asm volatile("cp.async.wait_group %0;" :: "n"(N) : "memory")

__device__ __forceinline__ void mma_tf32_16_8_8(float* c, const uint32_t* a,
                                                uint32_t b0, uint32_t b1) {
    asm volatile(
        "mma.sync.aligned.m16n8k8.row.col.f32.tf32.tf32.f32 "
        "{%0,%1,%2,%3}, {%4,%5,%6,%7}, {%8,%9}, {%0,%1,%2,%3};"
        : "+f"(c[0]), "+f"(c[1]), "+f"(c[2]), "+f"(c[3])
        : "r"(a[0]), "r"(a[1]), "r"(a[2]), "r"(a[3]), "r"(b0), "r"(b1));
}

__device__ __forceinline__ uint32_t bf_as_tf32(uint16_t h) {
    __nv_bfloat16 b = *reinterpret_cast<__nv_bfloat16*>(&h);
    return __float_as_uint(__bfloat162float(b));
}

// fragment-order permutation for K=512 operand panels of 128 rows.
__device__ __forceinline__ size_t perm_idx(int r, int k) {
    return (size_t)(r >> 7) * 65536
         + (size_t)((((k >> 3) * 8 + ((r >> 4) & 7)) << 7)
         + (((r & 7) * 4 + (k & 3)) << 2)
         + ((r >> 3) & 1) + (((k >> 2) & 1) << 1));
}

// =====================================================================
// tensor-core tf32 GEMM: C[M,Nc] = A[M,512] @ Bt[Nc,512]^T (+bias)
// A, Bt in FRAGMENT layout. CTA 128x128, 4 warps (2m x 2n), warp 64x64.
// 2 CTAs/SM, 3-stage cp.async, 1 barrier/k-tile.
// SW-pipelined fragment double-buffer: kk+1 frags load under kk MMA burst.
// =====================================================================
#define GEMM_SMEM (3 * 8192 * 4)       // 3 stages x 32KB = 98304 B

__global__ __launch_bounds__(128, 2)
void gemm_mma(const float* __restrict__ A, const float* __restrict__ Bt,
              const float* __restrict__ bias, float* __restrict__ Cm, int Nc)
{
    extern __shared__ float sm[];
    float* stage[3] = { sm, sm + 8192, sm + 16384 };
    const int tid = threadIdx.x;
    const int bn_panel = blockIdx.x;
    const int bm_panel = blockIdx.y;
    const int wid = tid >> 5, lane = tid & 31;
    const int lr = lane >> 2, lc = lane & 3;
    const int wmg = (wid & 1) * 4;       // A 16-row-group base (0 or 4)
    const int wng = (wid >> 1) * 4;      // B 16-col-group base (0 or 4)

    const float* Ab = A  + (size_t)bm_panel * 65536;
    const float* Bb = Bt + (size_t)bn_panel * 65536;

    float c[4][8][4];
#pragma unroll
    for (int mt = 0; mt < 4; mt++)
#pragma unroll
        for (int nt = 0; nt < 8; nt++)
#pragma unroll
            for (int j = 0; j < 4; j++) c[mt][nt][j] = 0.f;

    auto issue_stage = [&](int buf, int t) {
        uint32_t sa = smem_u32(stage[buf]);
        const float* as = Ab + t * 4096;
        const float* bs = Bb + t * 4096;
#pragma unroll
        for (int i = 0; i < 8; i++) {
            int ch = tid + i * 128;
            cp_async16(sa + ch * 16, as + ch * 4);
        }
#pragma unroll
        for (int i = 0; i < 8; i++) {
            int ch = tid + i * 128;
            cp_async16(sa + 16384 + ch * 16, bs + ch * 4);
        }
        CP_COMMIT();
    };

    issue_stage(0, 0);
    issue_stage(1, 1);

    for (int t = 0; t < 16; t++) {
        CP_WAIT(1);
        __syncthreads();
        if (t + 2 < 16) issue_stage((t + 2) % 3, t + 2);
        else            CP_COMMIT();

        const float4* sa4 = (const float4*)stage[t % 3];
        const float4* sb4 = (const float4*)(stage[t % 3] + 4096);

        // fragment double-buffer
        float4 fa[2][4], fb[2][4];
#pragma unroll
        for (int mt = 0; mt < 4; mt++)
            fa[0][mt] = sa4[(wmg + mt) * 32 + lane];
#pragma unroll
        for (int p = 0; p < 4; p++)
            fb[0][p] = sb4[(wng + p) * 32 + lane];

#pragma unroll
        for (int kk = 0; kk < 4; kk++) {
            const int cb = kk & 1, nb = cb ^ 1;
            if (kk < 3) {       // preload next phase BEFORE this phase's MMAs
#pragma unroll
                for (int mt = 0; mt < 4; mt++)
                    fa[nb][mt] = sa4[((kk + 1) * 8 + wmg + mt) * 32 + lane];
#pragma unroll
                for (int p = 0; p < 4; p++)
                    fb[nb][p] = sb4[((kk + 1) * 8 + wng + p) * 32 + lane];
            }
#pragma unroll
            for (int mt = 0; mt < 4; mt++) {
                uint32_t a[4];
                a[0] = __float_as_uint(fa[cb][mt].x);
                a[1] = __float_as_uint(fa[cb][mt].y);
                a[2] = __float_as_uint(fa[cb][mt].z);
                a[3] = __float_as_uint(fa[cb][mt].w);
#pragma unroll
                for (int p = 0; p < 4; p++) {
                    mma_tf32_16_8_8(c[mt][2 * p],
                                    a, __float_as_uint(fb[cb][p].x),
                                       __float_as_uint(fb[cb][p].z));
                    mma_tf32_16_8_8(c[mt][2 * p + 1],
                                    a, __float_as_uint(fb[cb][p].y),
                                       __float_as_uint(fb[cb][p].w));
                }
            }
        }
    }

#pragma unroll
    for (int mt = 0; mt < 4; mt++) {
        int row = bm_panel * 128 + (wid & 1) * 64 + mt * 16 + lr;
#pragma unroll
        for (int nt = 0; nt < 8; nt++) {
            int col = bn_panel * 128 + (wid >> 1) * 64 + nt * 8 + lc * 2;
            float2 v0 = make_float2(c[mt][nt][0], c[mt][nt][1]);
            float2 v1 = make_float2(c[mt][nt][2], c[mt][nt][3]);
            if (bias) {
                float b0 = bias[col], b1 = bias[col + 1];
                v0.x += b0; v0.y += b1;
                v1.x += b0; v1.y += b1;
            }
            *(float2*)&Cm[(size_t)row * Nc + col] = v0;
            *(float2*)&Cm[(size_t)(row + 8) * Nc + col] = v1;
        }
    }
}

// =====================================================================
// weight transposes -> fragment layout, tf32
// =====================================================================
__global__ void transpose_qgkv(const float* __restrict__ qg_w,
                               const float* __restrict__ kv_w)
{
    __shared__ float t[32][33];
    int bx = blockIdx.x * 32;
    int by = blockIdx.y * 32;
    int x = threadIdx.x, y = threadIdx.y;
    const float* W = (bx < 1024) ? qg_w : kv_w;
    int nb = bx & 1023;
#pragma unroll
    for (int j = 0; j < 32; j += 8)
        t[y + j][x] = W[(size_t)(by + y + j) * 1024 + nb + x];
    __syncthreads();
#pragma unroll
    for (int j = 0; j < 32; j += 8)
        d_wtc[perm_idx(bx + y + j, by + x)] = to_tf32(t[x][y + j]);
}

__global__ void transpose_w(const float* __restrict__ W, float* __restrict__ Wt, int Nc)
{
    __shared__ float t[32][33];
    int bx = blockIdx.x * 32;
    int by = blockIdx.y * 32;
    int x = threadIdx.x, y = threadIdx.y;
#pragma unroll
    for (int j = 0; j < 32; j += 8)
        t[y + j][x] = W[(size_t)(by + y + j) * Nc + bx + x];
    __syncthreads();
#pragma unroll
    for (int j = 0; j < 32; j += 8)
        Wt[perm_idx(bx + y + j, by + x)] = to_tf32(t[x][y + j]);
}

// =====================================================================
// x -> tf32 fragment layout
// =====================================================================
__global__ void permute_x(const float* __restrict__ x)
{
    int idx = blockIdx.x * 256 + threadIdx.x;
    int r = idx >> 7;
    int k = (idx & 127) * 4;
    float4 v = ((const float4*)x)[idx];
    size_t base = perm_idx(r, k);
    d_xr[base]      = to_tf32(v.x);
    d_xr[base + 4]  = to_tf32(v.y);
    d_xr[base + 8]  = to_tf32(v.z);
    d_xr[base + 12] = to_tf32(v.w);
}

// =====================================================================
// per-channel params
// =====================================================================
__global__ void prep_params(const float* __restrict__ scale_p,
                            const float* __restrict__ power_p)
{
    int c = threadIdx.x;
    d_scinv[c] = 1.f / log1pf(expf(scale_p[c]));
    d_pw[c] = 1.f + 4.f / (1.f + expf(-power_p[c]));
}

// =====================================================================
// features + fused km
// =====================================================================
__global__ __launch_bounds__(512)
void features_kernel(const float* __restrict__ pos_enc)
{
    int c   = threadIdx.x;
    int h   = c >> 6;
    int d   = c & 63;
    int bn0 = blockIdx.x * 16;
    int b   = bn0 / Nn;
    int n0  = bn0 - b * Nn;

    float scinv = d_scinv[c];
    float pw    = d_pw[c];
    float skp = 0.f, skn = 0.f;

#pragma unroll 4
    for (int i = 0; i < 16; i++) {
        int bn_ = bn0 + i;
        int n   = n0 + i;
        float qv  = d_qgkv[(size_t)bn_ * 2048 + c] * scinv;
        float kvv = (d_qgkv[(size_t)bn_ * 2048 + 1024 + c] + pos_enc[n * Cn + c]) * scinv;

        float qa = exp2f(pw * __log2f(fabsf(qv)));
        float ka = exp2f(pw * __log2f(fabsf(kvv)));
        float qp = (qv  > 0.f) ? qa : 0.f;
        float qn = (qv  < 0.f) ? qa : 0.f;
        float kp = (kvv > 0.f) ? ka : 0.f;
        float kn = (kvv < 0.f) ? ka : 0.f;

        size_t fbase = ((size_t)(b * NH + h) * Nn + n) * Fn;
        d_qf[fbase + d]      = __float2bfloat16_rn(qp);
        d_qf[fbase + 64 + d] = __float2bfloat16_rn(qn);
        d_kf[fbase + d]      = __float2bfloat16_rn(kp);
        d_kf[fbase + 64 + d] = __float2bfloat16_rn(kn);
        skp += kp; skn += kn;
    }
    const float inv_n = 1.f / (float)Nn;
    atomicAdd(&d_km[(b * NH + h) * Fn + d],      skp * inv_n);
    atomicAdd(&d_km[(b * NH + h) * Fn + 64 + d], skn * inv_n);
}

// =====================================================================
// zero km + kvm accumulators
// =====================================================================
__global__ void zero_aux_kernel()
{
    int i = blockIdx.x * blockDim.x + threadIdx.x;
    int stride = gridDim.x * blockDim.x;
    if (i < Bn * NH * Fn) d_km[i] = 0.f;
    for (int j = i; j < Bn * NH * Fn * 64; j += stride) d_kvm[j] = 0.f;
}

// =====================================================================
// kvm via mma (4 segments)
// =====================================================================
#define KV_SEG 784

__global__ __launch_bounds__(256)
void kvm_mma()
{
    __shared__ __align__(16) uint16_t kfs[2][32][136];
    __shared__ __align__(16) float    vss[2][32][72];
    int bh = blockIdx.x, seg = blockIdx.y;
    int b = bh >> 3, h = bh & 7;
    int tid = threadIdx.x, wid = tid >> 5, lane = tid & 31;
    int lr = lane >> 2, lc = lane & 3;
    int wd = (wid & 1) * 64;
    int we = (wid >> 1) * 16;

    float c[4][2][4];
#pragma unroll
    for (int mt = 0; mt < 4; mt++)
#pragma unroll
        for (int nt = 0; nt < 2; nt++)
#pragma unroll
            for (int j = 0; j < 4; j++) c[mt][nt][j] = 0.f;

    int nbase = seg * KV_SEG;
#pragma unroll
    for (int j = 0; j < 2; j++) {
        int idx = tid + j * 256;
        int r = idx >> 4, cs = idx & 15;
        cp_async16(smem_u32(&kfs[0][r][cs * 8]),
                   &d_kf[((size_t)bh * Nn + nbase + r) * 128 + cs * 8]);
        cp_async16(smem_u32(&vss[0][r][cs * 4]),
                   &d_qgkv[((size_t)(b * Nn) + nbase + r) * 2048 + 1536 + h * 64 + cs * 4]);
    }
    CP_COMMIT();

    // 784 rows per segment: 24 full 32-row tiles + one 16-row tail tile.
    const int NT = 25;
    for (int t = 0; t < NT; t++) {
        if (t + 1 < NT) {
            int nb = (t + 1) & 1;
            int n0 = nbase + (t + 1) * 32;
            int rows = (t + 1 == NT - 1) ? 16 : 32;
#pragma unroll
            for (int j = 0; j < 2; j++) {
                int idx = tid + j * 256;
                int r = idx >> 4, cs = idx & 15;
                if (r < rows) {
                    cp_async16(smem_u32(&kfs[nb][r][cs * 8]),
                               &d_kf[((size_t)bh * Nn + n0 + r) * 128 + cs * 8]);
                    cp_async16(smem_u32(&vss[nb][r][cs * 4]),
                               &d_qgkv[((size_t)(b * Nn) + n0 + r) * 2048 + 1536 + h * 64 + cs * 4]);
                } else {
                    *(float4*)((char*)&kfs[nb][r][cs * 8]) = make_float4(0.f, 0.f, 0.f, 0.f);
                    *(float4*)&vss[nb][r][cs * 4] = make_float4(0.f, 0.f, 0.f, 0.f);
                }
            }
            CP_COMMIT();
            CP_WAIT(1);
        } else {
            CP_WAIT(0);
        }
        __syncthreads();
        int buf = t & 1;
#pragma unroll
        for (int kk = 0; kk < 4; kk++) {
            int k0 = kk * 8;
            uint32_t a[4][4];
#pragma unroll
            for (int mt = 0; mt < 4; mt++) {
                int db = wd + mt * 16;
                a[mt][0] = bf_as_tf32(kfs[buf][k0 + lc][db + lr]);
                a[mt][1] = bf_as_tf32(kfs[buf][k0 + lc][db + lr + 8]);
                a[mt][2] = bf_as_tf32(kfs[buf][k0 + lc + 4][db + lr]);
                a[mt][3] = bf_as_tf32(kfs[buf][k0 + lc + 4][db + lr + 8]);
            }
#pragma unroll
            for (int nt = 0; nt < 2; nt++) {
                int eb = we + nt * 8;
                uint32_t b0 = __float_as_uint(vss[buf][k0 + lc][eb + lr]);
                uint32_t b1 = __float_as_uint(vss[buf][k0 + lc + 4][eb + lr]);
#pragma unroll
                for (int mt = 0; mt < 4; mt++)
                    mma_tf32_16_8_8(c[mt][nt], a[mt], b0, b1);
            }
        }
        __syncthreads();
    }

    const float inv_n = 1.f / (float)Nn;
    float* dst = &d_kvm[(size_t)bh * 8192];
#pragma unroll
    for (int mt = 0; mt < 4; mt++) {
        int d0 = wd + mt * 16 + lr;
#pragma unroll
        for (int nt = 0; nt < 2; nt++) {
            int e0 = we + nt * 8 + 2 * lc;
            atomicAdd(&dst[d0 * 64 + e0],           c[mt][nt][0] * inv_n);
            atomicAdd(&dst[d0 * 64 + e0 + 1],       c[mt][nt][1] * inv_n);
            atomicAdd(&dst[(d0 + 8) * 64 + e0],     c[mt][nt][2] * inv_n);
            atomicAdd(&dst[(d0 + 8) * 64 + e0 + 1], c[mt][nt][3] * inv_n);
        }
    }
}

// =====================================================================
// build KVM2
// =====================================================================
__global__ void build_kvm2()
{
    int bh = blockIdx.x;
    const float* kvm = &d_kvm[(size_t)bh * 8192];
    const float* km  = &d_km[bh * 128];
    float* out = &d_kvm2[(size_t)bh * 9216];
    for (int i = threadIdx.x; i < 128 * 72; i += 256) {
        int dd = i / 72, col = i - dd * 72;
        float v;
        if (col < 32)       v = kvm[dd * 64 + col];
        else if (col < 64)  v = kvm[(dd ^ 64) * 64 + col];
        else if (col == 64) v = km[dd];
        else if (col == 65) v = km[dd ^ 64];
        else                v = 0.f;
        out[i] = v;
    }
}

// =====================================================================
// attention via mma; scatter-stores d_t in FRAGMENT layout
// =====================================================================
#define ATT_SMEM (36864 + 17408)

__global__ __launch_bounds__(128)
void attn_mma()
{
    extern __shared__ char smx[];
    float*    Bsm = (float*)smx;
    uint16_t* Asm = (uint16_t*)(smx + 36864);
    int m0 = blockIdx.x * 64, bh = blockIdx.y;
    int b = bh >> 3, h = bh & 7;
    int tid = threadIdx.x, wid = tid >> 5, lane = tid & 31;
    int lr = lane >> 2, lc = lane & 3;
    int wm = wid * 16;

    {
        const char* bsrc = (const char*)&d_kvm2[(size_t)bh * 9216];
#pragma unroll
        for (int j = 0; j < 18; j++) {
            int idx = tid + j * 128;
            cp_async16(smem_u32((char*)Bsm + idx * 16), bsrc + idx * 16);
        }
#pragma unroll
        for (int j = 0; j < 8; j++) {
            int idx = tid + j * 128;
            int r = idx >> 4, cs = idx & 15;
            cp_async16(smem_u32(&Asm[r * 136 + cs * 8]),
                       &d_qf[((size_t)bh * Nn + m0 + r) * 128 + cs * 8]);
        }
        CP_COMMIT(); CP_WAIT(0);
    }
    __syncthreads();

    float c[9][4];
#pragma unroll
    for (int nt = 0; nt < 9; nt++)
#pragma unroll
        for (int j = 0; j < 4; j++) c[nt][j] = 0.f;

#pragma unroll
    for (int kt = 0; kt < 16; kt++) {
        int k0 = kt * 8;
        uint32_t a[4];
        a[0] = bf_as_tf32(Asm[(wm + lr) * 136 + k0 + lc]);
        a[1] = bf_as_tf32(Asm[(wm + lr + 8) * 136 + k0 + lc]);
        a[2] = bf_as_tf32(Asm[(wm + lr) * 136 + k0 + lc + 4]);
        a[3] = bf_as_tf32(Asm[(wm + lr + 8) * 136 + k0 + lc + 4]);
#pragma unroll
        for (int nt = 0; nt < 9; nt++) {
            uint32_t b0 = __float_as_uint(Bsm[(k0 + lc) * 72 + nt * 8 + lr]);
            uint32_t b1 = __float_as_uint(Bsm[(k0 + lc + 4) * 72 + nt * 8 + lr]);
            mma_tf32_16_8_8(c[nt], a, b0, b1);
        }
    }

    int src = lane & 28;
    float den1a = __shfl_sync(0xffffffffu, c[8][0], src);
    float den2a = __shfl_sync(0xffffffffu, c[8][1], src);
    float den1b = __shfl_sync(0xffffffffu, c[8][2], src);
    float den2b = __shfl_sync(0xffffffffu, c[8][3], src);
    float z1a = 1.f / (den1a + 1e-6f), z2a = 1.f / (den2a + 1e-6f);
    float z1b = 1.f / (den1b + 1e-6f), z2b = 1.f / (den2b + 1e-6f);

    int ra = b * Nn + m0 + wm + lr;
    int rb = ra + 8;
#pragma unroll
    for (int nt = 0; nt < 8; nt++) {
        int col = nt * 8 + 2 * lc;
        float za = (col < 32) ? z1a : z2a;
        float zb = (col < 32) ? z1b : z2b;
        int k = h * 64 + col;
        d_t[perm_idx(ra, k)]     = c[nt][0] * za;
        d_t[perm_idx(ra, k + 1)] = c[nt][1] * za;
        d_t[perm_idx(rb, k)]     = c[nt][2] * zb;
        d_t[perm_idx(rb, k + 1)] = c[nt][3] * zb;
    }
}

// =====================================================================
// depthwise conv + gate; d_t accessed via fragment indices, stores tf32
// =====================================================================
__global__ __launch_bounds__(512)
void conv_gate_kernel(const float* __restrict__ dwc_w,
                      const float* __restrict__ dwc_b)
{
    __shared__ float ws[64 * 25];
    __shared__ float bs[64];
    int y = blockIdx.x;
    int b = blockIdx.y;
    int c = threadIdx.x;
    int d = c & 63;
    for (int i = c; i < 64 * 25; i += 512) ws[i] = dwc_w[i];
    if (c < 64) bs[c] = dwc_b[c];
    __syncthreads();

    const float* vbase = &d_qgkv[(size_t)(b * Nn) * 2048 + 1536 + c];

    float win[5][5];
#pragma unroll
    for (int dy = 0; dy < 5; dy++) {
        int yy = y + dy - 2;
        bool yok = (unsigned)yy < HW;
#pragma unroll
        for (int j = 0; j < 5; j++) {
            int xx = j - 2;
            win[dy][j] = (yok && (unsigned)xx < HW)
                         ? vbase[(size_t)(yy * HW + xx) * 2048] : 0.f;
        }
    }

    for (int x = 0; x < HW; x++) {
        float acc = bs[d];
#pragma unroll
        for (int dy = 0; dy < 5; dy++)
#pragma unroll
            for (int j = 0; j < 5; j++)
                acc = fmaf(win[dy][j], ws[d * 25 + dy * 5 + j], acc);

        int i1 = b * Nn + y * HW + x;
        float g = d_qgkv[(size_t)i1 * 2048 + 512 + c];
        size_t pi = perm_idx(i1, c);
        d_t[pi] = to_tf32((d_t[pi] + acc) * g);

        int xx = x + 3;
        bool xok = xx < HW;
#pragma unroll
        for (int dy = 0; dy < 5; dy++) {
#pragma unroll
            for (int j = 0; j < 4; j++) win[dy][j] = win[dy][j + 1];
            int yy = y + dy - 2;
            win[dy][4] = (xok && (unsigned)yy < HW)
                         ? vbase[(size_t)(yy * HW + xx) * 2048] : 0.f;
        }
    }
}

// =====================================================================
// launch (launch #3 == big gemm for ncu capture)
// =====================================================================
extern "C" void kernel_launch(void* const* d_in, const int* in_sizes, int n_in,
                              void* d_out, int out_size)
{
    const float* x       = (const float*)d_in[0];
    const float* qg_w    = (const float*)d_in[1];
    const float* kv_w    = (const float*)d_in[2];
    const float* proj_w  = (const float*)d_in[3];
    const float* proj_b  = (const float*)d_in[4];
    const float* pos_enc = (const float*)d_in[5];
    const float* scale_p = (const float*)d_in[6];
    const float* power_p = (const float*)d_in[7];
    const float* dwc_w   = (const float*)d_in[8];
    const float* dwc_b   = (const float*)d_in[9];
    float* out = (float*)d_out;

    float *p_qgkv, *p_t, *p_wtc, *p_wt3, *p_xr;
    cudaGetSymbolAddress((void**)&p_qgkv, d_qgkv);
    cudaGetSymbolAddress((void**)&p_t,    d_t);
    cudaGetSymbolAddress((void**)&p_wtc,  d_wtc);
    cudaGetSymbolAddress((void**)&p_wt3,  d_wt3);
    cudaGetSymbolAddress((void**)&p_xr,   d_xr);

    cudaFuncSetAttribute(gemm_mma, cudaFuncAttributeMaxDynamicSharedMemorySize,
                         GEMM_SMEM);
    cudaFuncSetAttribute(attn_mma, cudaFuncAttributeMaxDynamicSharedMemorySize,
                         ATT_SMEM);

    dim3 tb(32, 8);
    prep_params<<<1, 512>>>(scale_p, power_p);                       // 0
    permute_x<<<Mrows * 128 / 256, 256>>>(x);                        // 1
    transpose_qgkv<<<dim3(64, 16), tb>>>(qg_w, kv_w);                // 2
    gemm_mma<<<dim3(16, Mrows / 128), 128, GEMM_SMEM>>>(             // 3 (profiled)
        p_xr, p_wtc, nullptr, p_qgkv, 2048);
    transpose_w<<<dim3(16, 16), tb>>>(proj_w, p_wt3, 512);           // 4
    zero_aux_kernel<<<1024, 256>>>();                                // 5
    features_kernel<<<Mrows / 16, 512>>>(pos_enc);                   // 6
    kvm_mma<<<dim3(Bn * NH, 4), 256>>>();                            // 7
    build_kvm2<<<Bn * NH, 256>>>();                                  // 8
    attn_mma<<<dim3(Nn / 64, Bn * NH), 128, ATT_SMEM>>>();           // 9
    conv_gate_kernel<<<dim3(HW, Bn), 512>>>(dwc_w, dwc_b);           // 10
    gemm_mma<<<dim3(4, Mrows / 128), 128, GEMM_SMEM>>>(              // 11
        p_t, p_wt3, proj_b, out, 512);
}